// round 14
// baseline (speedup 1.0000x reference)
#include <cuda_runtime.h>
#include <cuda_bf16.h>
#include <math.h>
#include <stdint.h>

// B=4, C=256, H=W=32, NH=8, HC=32, G=4, GC=64, ns=1024, KK=5, ORF=2
typedef unsigned long long u64;

__device__ __forceinline__ uint32_t cvt_tf32(float x) {
    uint32_t r;
    asm("cvt.rna.tf32.f32 %0, %1;" : "=r"(r) : "f"(x));
    return r;
}
__device__ __forceinline__ void mma_tf32(float c[4],
                                         uint32_t a0, uint32_t a1, uint32_t a2, uint32_t a3,
                                         uint32_t b0, uint32_t b1) {
    asm("mma.sync.aligned.m16n8k8.row.col.f32.tf32.tf32.f32 "
        "{%0,%1,%2,%3}, {%4,%5,%6,%7}, {%8,%9}, {%0,%1,%2,%3};"
        : "+f"(c[0]), "+f"(c[1]), "+f"(c[2]), "+f"(c[3])
        : "r"(a0), "r"(a1), "r"(a2), "r"(a3), "r"(b0), "r"(b1));
}

// ---------------- scratch ----------------
__device__ float g_q [4 * 256 * 1024];
__device__ float g_xs[4 * 256 * 1024];
__device__ float g_k [4 * 256 * 1024];
__device__ float g_v [4 * 256 * 1024];
__device__ float g_o [4 * 256 * 1024];
__device__ float g_pos[16 * 1024 * 2];
__device__ float g_part[2 * 1048576];   // split-n partial outputs
__device__ float g_L[2 * 32768];        // split-n partial row sums

// ---------------- tf32 tensor-core SGEMM, double-buffered (R11 config) ------
__device__ __forceinline__ void gemm_tf32_body(const float* __restrict__ Wm,
                                               const float* __restrict__ Xb,
                                               const float* __restrict__ bias,
                                               float* __restrict__ Yb,
                                               int m0, int n0, uint32_t* sm)
{
    uint32_t* As = sm;           // [2][128 m][32 k] stride 36
    uint32_t* Bs = sm + 9216;    // [2][64 n][32 k]  stride 36

    const int tid  = threadIdx.x;
    const int w    = tid >> 5;
    const int lane = tid & 31;
    const int grp  = lane >> 2;
    const int tig  = lane & 3;
    const int mw   = w >> 1;
    const int nw   = w & 1;

    const int a_m = tid >> 5;
    const int a_c = tid & 31;
    const int b_c = tid >> 6;
    const int b_n = tid & 63;

    float acc[2][4][4];
#pragma unroll
    for (int mf = 0; mf < 2; mf++)
#pragma unroll
        for (int nf = 0; nf < 4; nf++)
#pragma unroll
            for (int j = 0; j < 4; j++) acc[mf][nf][j] = 0.f;

    const int rowA0 = (mw * 32 + grp) * 36;
    const int rowB0 = (nw * 32 + grp) * 36;

    float wr[16], xr[8];
#pragma unroll
    for (int t = 0; t < 16; t++)
        wr[t] = Wm[(m0 + t * 8 + a_m) * 256 + a_c];
#pragma unroll
    for (int t = 0; t < 8; t++)
        xr[t] = Xb[(t * 4 + b_c) * 1024 + n0 + b_n];

    for (int kc = 0; kc < 8; kc++) {
        uint32_t* As_b = As + (kc & 1) * 4608;
        uint32_t* Bs_b = Bs + (kc & 1) * 2304;
#pragma unroll
        for (int t = 0; t < 16; t++)
            As_b[(t * 8 + a_m) * 36 + a_c] = cvt_tf32(wr[t]);
#pragma unroll
        for (int t = 0; t < 8; t++)
            Bs_b[b_n * 36 + t * 4 + b_c] = cvt_tf32(xr[t]);
        __syncthreads();

        if (kc < 7) {
            const int k0 = (kc + 1) * 32;
#pragma unroll
            for (int t = 0; t < 16; t++)
                wr[t] = Wm[(m0 + t * 8 + a_m) * 256 + k0 + a_c];
#pragma unroll
            for (int t = 0; t < 8; t++)
                xr[t] = Xb[(k0 + t * 4 + b_c) * 1024 + n0 + b_n];
        }

#pragma unroll
        for (int kk = 0; kk < 4; kk++) {
            const int kb = kk * 8 + tig;
            uint32_t a00 = As_b[rowA0 + kb];
            uint32_t a01 = As_b[rowA0 + 288 + kb];
            uint32_t a02 = As_b[rowA0 + kb + 4];
            uint32_t a03 = As_b[rowA0 + 288 + kb + 4];
            uint32_t a10 = As_b[rowA0 + 576 + kb];
            uint32_t a11 = As_b[rowA0 + 864 + kb];
            uint32_t a12 = As_b[rowA0 + 576 + kb + 4];
            uint32_t a13 = As_b[rowA0 + 864 + kb + 4];
#pragma unroll
            for (int nf = 0; nf < 4; nf++) {
                uint32_t b0 = Bs_b[rowB0 + nf * 288 + kb];
                uint32_t b1 = Bs_b[rowB0 + nf * 288 + kb + 4];
                mma_tf32(acc[0][nf], a00, a01, a02, a03, b0, b1);
                mma_tf32(acc[1][nf], a10, a11, a12, a13, b0, b1);
            }
        }
    }

    const int mr0 = m0 + mw * 32 + grp;
#pragma unroll
    for (int mf = 0; mf < 2; mf++) {
        int r0 = mr0 + mf * 16;
        float b0 = bias[r0], b1 = bias[r0 + 8];
#pragma unroll
        for (int nf = 0; nf < 4; nf++) {
            int col = n0 + nw * 32 + nf * 8 + 2 * tig;
            float2 lo = make_float2(acc[mf][nf][0] + b0, acc[mf][nf][1] + b0);
            float2 hi = make_float2(acc[mf][nf][2] + b1, acc[mf][nf][3] + b1);
            *(float2*)&Yb[r0 * 1024 + col]       = lo;
            *(float2*)&Yb[(r0 + 8) * 1024 + col] = hi;
        }
    }
}

__global__ __launch_bounds__(256, 3)
void gemm_q_tf32(const float* __restrict__ Wm, const float* __restrict__ X,
                 const float* __restrict__ bias, float* __restrict__ Y)
{
    extern __shared__ uint32_t smq[];
    gemm_tf32_body(Wm, X + blockIdx.z * 262144, bias, Y + blockIdx.z * 262144,
                   blockIdx.y * 128, blockIdx.x * 64, smq);
}

__global__ __launch_bounds__(256, 3)
void gemm_kv_tf32(const float* __restrict__ Wk, const float* __restrict__ bk,
                  float* __restrict__ Yk,
                  const float* __restrict__ Wv, const float* __restrict__ bv,
                  float* __restrict__ Yv, const float* __restrict__ X)
{
    extern __shared__ uint32_t smkv[];
    const int my = blockIdx.y;
    const float* Xb = X + blockIdx.z * 262144;
    if (my < 2)
        gemm_tf32_body(Wk, Xb, bk, Yk + blockIdx.z * 262144, my * 128, blockIdx.x * 64, smkv);
    else
        gemm_tf32_body(Wv, Xb, bv, Yv + blockIdx.z * 262144, (my - 2) * 128, blockIdx.x * 64, smkv);
}

// ---------------- offset pipeline: smem-staged conv, activations cached -----
__global__ __launch_bounds__(256)
void offset_kernel(const float* __restrict__ q, const float* __restrict__ w_dw,
                   const float* __restrict__ b_dw, const float* __restrict__ ln_g,
                   const float* __restrict__ ln_b, const float* __restrict__ wpj,
                   float* __restrict__ pos_buf, float* __restrict__ out_pos,
                   float* __restrict__ out_ref)
{
    extern __shared__ float dsm[];
    float* simg = dsm;               // [c][384]
    float* sa   = dsm + 64 * 384;    // [c][256]

    __shared__ float sw[1600];
    __shared__ float sb[64], sg[64], sbt[64], spj0[64], spj1[64];

    const int tid = threadIdx.x;
    for (int t = tid; t < 1600; t += 256) sw[t] = w_dw[t];
    if (tid < 64) {
        sb[tid] = b_dw[tid]; sg[tid] = ln_g[tid]; sbt[tid] = ln_b[tid];
        spj0[tid] = wpj[tid]; spj1[tid] = wpj[64 + tid];
    }

    const int bi = blockIdx.x;
    const int bg = bi >> 2;
    const int i0 = (bi & 3) * 8;
    const float* qb = q + bg * 65536;

    for (int t = tid; t < 24576; t += 256) {
        int c  = t / 384;
        int r2 = t - c * 384;
        int yy = i0 - 2 + (r2 >> 5);
        int col = r2 & 31;
        float vv = 0.f;
        if ((unsigned)yy < 32u) vv = qb[c * 1024 + yy * 32 + col];
        simg[c * 384 + r2] = vv;
    }
    __syncthreads();

    const int li = tid >> 5;
    const int j  = tid & 31;
    const int i  = i0 + li;

    float s1 = 0.f, s2 = 0.f;
    for (int c = 0; c < 64; c++) {
        const float* ic = simg + c * 384 + li * 32;
        const float* wc = sw + c * 25;
        float a = sb[c];
#pragma unroll
        for (int dy = 0; dy < 5; dy++) {
            const float* irow = ic + dy * 32;
#pragma unroll
            for (int dx = 0; dx < 5; dx++) {
                int xx = j + dx - 2;
                float vv = ((unsigned)xx < 32u) ? irow[xx] : 0.f;
                a = fmaf(vv, wc[dy * 5 + dx], a);
            }
        }
        s1 += a;
        s2 = fmaf(a, a, s2);
        sa[c * 256 + tid] = a;
    }
    float mu   = s1 * 0.015625f;
    float var  = s2 * 0.015625f - mu * mu;
    float rstd = rsqrtf(var + 1e-5f);

    float o0 = 0.f, o1 = 0.f;
    for (int c = 0; c < 64; c++) {
        float a  = sa[c * 256 + tid];
        float t2 = fmaf((a - mu) * rstd, sg[c], sbt[c]);
        float gl = 0.5f * t2 * (1.f + erff(t2 * 0.70710678118654752f));
        o0 = fmaf(gl, spj0[c], o0);
        o1 = fmaf(gl, spj1[c], o1);
    }
    float off0 = tanhf(o0) * 0.0625f;
    float off1 = tanhf(o1) * 0.0625f;
    float r0 = (j + 0.5f) * 0.0625f - 1.f;
    float r1 = (i + 0.5f) * 0.0625f - 1.f;
    float P0 = off0 + r0, P1 = off1 + r1;

    const int pix = bi * 256 + tid;
    pos_buf[pix * 2]     = P0;
    pos_buf[pix * 2 + 1] = P1;
    out_pos[pix * 2]     = P0;
    out_pos[pix * 2 + 1] = P1;
    out_ref[pix * 2]     = r0;
    out_ref[pix * 2 + 1] = r1;
}

// ---------------- bilinear sample of x at pos -> xs --------------------------
__global__ __launch_bounds__(256)
void sample_kernel(const float* __restrict__ x, const float* __restrict__ pos_buf,
                   float* __restrict__ xs)
{
    const int w    = threadIdx.x >> 5;
    const int lane = threadIdx.x & 31;
    const int idx  = blockIdx.x * 32 + lane;   // 0..16383
    const float P0 = pos_buf[idx * 2];
    const float P1 = pos_buf[idx * 2 + 1];
    const float gxp = (P1 + 1.f) * 15.5f;
    const float gyp = (P0 + 1.f) * 15.5f;
    float x0f = floorf(gxp), y0f = floorf(gyp);
    float x1f = x0f + 1.f,  y1f = y0f + 1.f;
    float wx1 = gxp - x0f, wx0 = 1.f - wx1;
    float wy1 = gyp - y0f, wy0 = 1.f - wy1;
    bool vx0 = (x0f >= 0.f) && (x0f <= 31.f);
    bool vx1 = (x1f >= 0.f) && (x1f <= 31.f);
    bool vy0 = (y0f >= 0.f) && (y0f <= 31.f);
    bool vy1 = (y1f >= 0.f) && (y1f <= 31.f);
    int X0 = (int)fminf(fmaxf(x0f, 0.f), 31.f);
    int X1 = (int)fminf(fmaxf(x1f, 0.f), 31.f);
    int Y0 = (int)fminf(fmaxf(y0f, 0.f), 31.f);
    int Y1 = (int)fminf(fmaxf(y1f, 0.f), 31.f);
    float w00 = (vy0 && vx0) ? wy0 * wx0 : 0.f;
    float w01 = (vy0 && vx1) ? wy0 * wx1 : 0.f;
    float w10 = (vy1 && vx0) ? wy1 * wx0 : 0.f;
    float w11 = (vy1 && vx1) ? wy1 * wx1 : 0.f;
    int i00 = Y0 * 32 + X0, i01 = Y0 * 32 + X1;
    int i10 = Y1 * 32 + X0, i11 = Y1 * 32 + X1;

    const int bg = idx >> 10, n = idx & 1023;
    const float* xb = x + bg * 65536 + w * 8 * 1024;
    float* xo = xs + bg * 65536 + w * 8 * 1024 + n;
#pragma unroll
    for (int c = 0; c < 8; c++) {
        const float* xc = xb + c * 1024;
        float vout = w00 * xc[i00] + w01 * xc[i01] + w10 * xc[i10] + w11 * xc[i11];
        xo[c * 1024] = vout;
    }
}

// ---------------- RPE bilinear from bf16x2 PAIRED table ----------------------
__device__ __forceinline__ float bias_Pb(const uint32_t* __restrict__ sR,
                                         float gyp, float gxp)
{
    int yi = __float2int_rd(gyp);
    int xi = __float2int_rd(gxp);
    float wy1 = gyp - __int2float_rn(yi);
    float wx1 = gxp - __int2float_rn(xi);
    uint32_t w0 = sR[(xi << 6) + yi];
    uint32_t w1 = sR[(xi << 6) + 64 + yi];
    float p0x = __uint_as_float(w0 << 16);
    float p0y = __uint_as_float(w0 & 0xFFFF0000u);
    float p1x = __uint_as_float(w1 << 16);
    float p1y = __uint_as_float(w1 & 0xFFFF0000u);
    float v0 = fmaf(wy1, p0y - p0x, p0x);
    float v1 = fmaf(wy1, p1y - p1x, p1x);
    return fmaf(wx1, v1 - v0, v0);
}

// ---------------- fused attention, SPLIT-N (z in {0,1}, 8 tiles each) --------
// grid (8, 32, 2) = 512 blocks -> ~3.3 blocks/SM resident at occ 3.
// Emits unnormalized acc into g_part[z] and per-row L into g_L[z].
__global__ __launch_bounds__(256, 3)
void attn_mma(const float* __restrict__ q, const float* __restrict__ k,
              const float* __restrict__ v, const float* __restrict__ rpe,
              const float* __restrict__ pos, float* __restrict__ part,
              float* __restrict__ partL)
{
    extern __shared__ float smf[];
    uint32_t* sQ   = (uint32_t*)smf;           // 4608
    uint32_t* sK   = sQ + 4608;                // 2 x 2304
    uint32_t* sV   = sK + 4608;                // 2 x 2304
    float*    sPos = (float*)(sV + 4608);      // 2 x 128
    uint32_t* sRb  = (uint32_t*)(sPos + 256);  // 4096 (bf16x2 pairs)

    const int bh = blockIdx.y;
    const int b  = bh >> 3, h = bh & 7;
    const int gq = h >> 1;
    const int bg = b * 4 + gq;
    const int m0 = blockIdx.x * 128;
    const int z  = blockIdx.z;
    const int nz = z * 512;                    // n-range start
    const float* rpe_h = rpe + h * 3969;

    const int tid  = threadIdx.x;
    const int w    = tid >> 5;
    const int lane = tid & 31;
    const int grp  = lane >> 2;
    const int tig  = lane & 3;
    const int pgrp = (grp & 1) ? (grp >> 1) + 4 : (grp >> 1);

    for (int t = tid; t < 4096; t += 256) sRb[t] = 0u;
    __syncthreads();
    {
        __nv_bfloat16* sRh = (__nv_bfloat16*)sRb;
        for (int t = tid; t < 3969; t += 256) {
            int r = t / 63, c2 = t - r * 63;
            __nv_bfloat16 bv = __float2bfloat16(rpe_h[t]);
            sRh[(((c2 << 6) + r) << 1)] = bv;
            if (r > 0) sRh[(((c2 << 6) + r - 1) << 1) + 1] = bv;
        }
    }

    const float* qh = q + (b * 256 + h * 32) * 1024;
    const float* kh = k + (b * 256 + h * 32) * 1024;
    const float* vh = v + (b * 256 + h * 32) * 1024;

    for (int idx = tid; idx < 4096; idx += 256) {
        int c = idx >> 7, mm = idx & 127;
        sQ[mm * 36 + c] = cvt_tf32(qh[c * 1024 + m0 + mm]);
    }

    const int mg0 = m0 + w * 16 + grp;
    const int mg1 = mg0 + 8;
    const float cg00 = fmaf(((mg0 & 31) + 0.5f) * 0.0625f - 1.f, 15.5f, 31.f);
    const float cg01 = fmaf(((mg0 >> 5) + 0.5f) * 0.0625f - 1.f, 15.5f, 31.f);
    const float cg10 = fmaf(((mg1 & 31) + 0.5f) * 0.0625f - 1.f, 15.5f, 31.f);
    const float cg11 = fmaf(((mg1 >> 5) + 0.5f) * 0.0625f - 1.f, 15.5f, 31.f);

    const int rowA0 = (w * 16 + grp) * 36;
    const int rowA1 = rowA0 + 8 * 36;

    float accv[4][4];
#pragma unroll
    for (int vf = 0; vf < 4; vf++)
#pragma unroll
        for (int j = 0; j < 4; j++) accv[vf][j] = 0.f;
    float L0 = 0.f, L1 = 0.f;

    const float scale = 0.17677669529663687f;

    const int st_c = tid >> 6;    // 0..3
    const int st_n = tid & 63;
    float kf[8], vfr[8], posr;
#pragma unroll
    for (int t = 0; t < 8; t++) {
        kf[t]  = kh[(t * 4 + st_c) * 1024 + nz + st_n];
        vfr[t] = vh[(t * 4 + st_c) * 1024 + nz + st_n];
    }
    posr = (tid < 128) ? pos[bg * 2048 + nz * 2 + tid] : 0.f;

    for (int nt = 0; nt < 8; nt++) {
        uint32_t* sKb = sK + (nt & 1) * 2304;
        uint32_t* sVb = sV + (nt & 1) * 2304;
        float*    sPb = sPos + (nt & 1) * 128;
#pragma unroll
        for (int t = 0; t < 8; t++) {
            sKb[st_n * 36 + t * 4 + st_c] = cvt_tf32(kf[t]);
            sVb[st_n * 36 + t * 4 + st_c] = cvt_tf32(vfr[t]);
        }
        if (tid < 128) sPb[tid] = posr;
        __syncthreads();

        if (nt < 7) {
            const int n0n = nz + (nt + 1) * 64;
#pragma unroll
            for (int t = 0; t < 8; t++) {
                kf[t]  = kh[(t * 4 + st_c) * 1024 + n0n + st_n];
                vfr[t] = vh[(t * 4 + st_c) * 1024 + n0n + st_n];
            }
            posr = (tid < 128) ? pos[bg * 2048 + n0n * 2 + tid] : 0.f;
        }

        // ---- QK with permuted B rows
        float sc[8][4];
#pragma unroll
        for (int nf = 0; nf < 8; nf++)
#pragma unroll
            for (int j = 0; j < 4; j++) sc[nf][j] = 0.f;

#pragma unroll
        for (int kk = 0; kk < 4; kk++) {
            const int k0 = kk * 8;
            uint32_t a0 = sQ[rowA0 + k0 + tig];
            uint32_t a1 = sQ[rowA1 + k0 + tig];
            uint32_t a2 = sQ[rowA0 + k0 + tig + 4];
            uint32_t a3 = sQ[rowA1 + k0 + tig + 4];
#pragma unroll
            for (int nf = 0; nf < 8; nf++) {
                uint32_t b0 = sKb[(nf * 8 + pgrp) * 36 + k0 + tig];
                uint32_t b1 = sKb[(nf * 8 + pgrp) * 36 + k0 + tig + 4];
                mma_tf32(sc[nf], a0, a1, a2, a3, b0, b1);
            }
        }

        // ---- bias + exp + PV; P stays in registers
#pragma unroll
        for (int nf = 0; nf < 8; nf++) {
            const int kb = nf * 8;
            float2 pA = *(const float2*)&sPb[2 * (kb + tig)];
            float2 pB = *(const float2*)&sPb[2 * (kb + tig + 4)];
            float pb0 = 15.5f * pA.x, pb1 = 15.5f * pA.y;
            float pb2 = 15.5f * pB.x, pb3 = 15.5f * pB.y;
            float e0 = __expf(fmaf(sc[nf][0], scale, bias_Pb(sRb, cg00 - pb0, cg01 - pb1)));
            float e1 = __expf(fmaf(sc[nf][1], scale, bias_Pb(sRb, cg00 - pb2, cg01 - pb3)));
            float e2 = __expf(fmaf(sc[nf][2], scale, bias_Pb(sRb, cg10 - pb0, cg11 - pb1)));
            float e3 = __expf(fmaf(sc[nf][3], scale, bias_Pb(sRb, cg10 - pb2, cg11 - pb3)));
            L0 += e0 + e1;
            L1 += e2 + e3;
            uint32_t a0 = cvt_tf32(e0);
            uint32_t a1 = cvt_tf32(e2);
            uint32_t a2 = cvt_tf32(e1);
            uint32_t a3 = cvt_tf32(e3);
#pragma unroll
            for (int vf = 0; vf < 4; vf++) {
                uint32_t b0 = sVb[(kb + tig) * 36 + vf * 8 + grp];
                uint32_t b1 = sVb[(kb + tig + 4) * 36 + vf * 8 + grp];
                mma_tf32(accv[vf], a0, a1, a2, a3, b0, b1);
            }
        }
    }

    L0 += __shfl_xor_sync(0xffffffffu, L0, 1);
    L0 += __shfl_xor_sync(0xffffffffu, L0, 2);
    L1 += __shfl_xor_sync(0xffffffffu, L1, 1);
    L1 += __shfl_xor_sync(0xffffffffu, L1, 2);

    float* pz = part + z * 1048576;
#pragma unroll
    for (int vf = 0; vf < 4; vf++) {
        int ch = h * 32 + vf * 8 + 2 * tig;
        int base = (b * 256 + ch) * 1024 + mg0;
        pz[base]            = accv[vf][0];
        pz[base + 1024]     = accv[vf][1];
        pz[base + 8]        = accv[vf][2];
        pz[base + 1024 + 8] = accv[vf][3];
    }
    if (tig == 0) {
        partL[z * 32768 + bh * 1024 + mg0] = L0;
        partL[z * 32768 + bh * 1024 + mg1] = L1;
    }
}

// ---------------- combine: out = (p0 + p1) / (L0 + L1) -----------------------
__global__ __launch_bounds__(256)
void combine_kernel(const float* __restrict__ part, const float* __restrict__ partL,
                    float* __restrict__ out)
{
    const int idx = blockIdx.x * 256 + threadIdx.x;   // 0 .. 1048575
    const int m   = idx & 1023;
    const int bch = idx >> 10;
    const int bh  = ((bch >> 8) << 3) + ((bch & 255) >> 5);
    float L = partL[bh * 1024 + m] + partL[32768 + bh * 1024 + m];
    out[idx] = (part[idx] + part[1048576 + idx]) / L;
}

// ---------------- launch ----------------
extern "C" void kernel_launch(void* const* d_in, const int* in_sizes, int n_in,
                              void* d_out, int out_size)
{
    const float* x        = (const float*)d_in[0];
    const float* wq       = (const float*)d_in[1];
    const float* bq       = (const float*)d_in[2];
    const float* w_off_dw = (const float*)d_in[3];
    const float* b_off_dw = (const float*)d_in[4];
    const float* ln_g     = (const float*)d_in[5];
    const float* ln_b     = (const float*)d_in[6];
    const float* w_off_pj = (const float*)d_in[7];
    const float* wk       = (const float*)d_in[8];
    const float* bk       = (const float*)d_in[9];
    const float* wv       = (const float*)d_in[10];
    const float* bv       = (const float*)d_in[11];
    const float* wo       = (const float*)d_in[12];
    const float* bo       = (const float*)d_in[13];
    const float* rpe      = (const float*)d_in[14];
    float* out = (float*)d_out;

    float *qb, *xsb, *kb, *vb, *ob, *posb, *partb, *partLb;
    cudaGetSymbolAddress((void**)&qb,     g_q);
    cudaGetSymbolAddress((void**)&xsb,    g_xs);
    cudaGetSymbolAddress((void**)&kb,     g_k);
    cudaGetSymbolAddress((void**)&vb,     g_v);
    cudaGetSymbolAddress((void**)&ob,     g_o);
    cudaGetSymbolAddress((void**)&posb,   g_pos);
    cudaGetSymbolAddress((void**)&partb,  g_part);
    cudaGetSymbolAddress((void**)&partLb, g_L);

    const int attn_smem = 72704;
    cudaFuncSetAttribute(attn_mma, cudaFuncAttributeMaxDynamicSharedMemorySize, attn_smem);
    const int gem_smem = 55296;
    cudaFuncSetAttribute(gemm_q_tf32, cudaFuncAttributeMaxDynamicSharedMemorySize, gem_smem);
    cudaFuncSetAttribute(gemm_kv_tf32, cudaFuncAttributeMaxDynamicSharedMemorySize, gem_smem);
    const int off_smem = 163840;
    cudaFuncSetAttribute(offset_kernel, cudaFuncAttributeMaxDynamicSharedMemorySize, off_smem);

    gemm_q_tf32<<<dim3(16, 2, 4), 256, gem_smem>>>(wq, x, bq, qb);
    offset_kernel<<<64, 256, off_smem>>>(qb, w_off_dw, b_off_dw, ln_g, ln_b, w_off_pj,
                                         posb, out + 1048576, out + 1048576 + 32768);
    sample_kernel<<<512, 256>>>(x, posb, xsb);
    gemm_kv_tf32<<<dim3(16, 4, 4), 256, gem_smem>>>(wk, bk, kb, wv, bv, vb, xsb);
    attn_mma<<<dim3(8, 32, 2), 256, attn_smem>>>(qb, kb, vb, rpe, posb, partb, partLb);
    combine_kernel<<<4096, 256>>>(partb, partLb, ob);
    gemm_q_tf32<<<dim3(16, 2, 4), 256, gem_smem>>>(wo, ob, bo, out);
}

// round 15
// speedup vs baseline: 1.0781x; 1.0781x over previous
#include <cuda_runtime.h>
#include <cuda_bf16.h>
#include <math.h>
#include <stdint.h>

// B=4, C=256, H=W=32, NH=8, HC=32, G=4, GC=64, ns=1024, KK=5, ORF=2
typedef unsigned long long u64;

__device__ __forceinline__ uint32_t cvt_tf32(float x) {
    uint32_t r;
    asm("cvt.rna.tf32.f32 %0, %1;" : "=r"(r) : "f"(x));
    return r;
}
__device__ __forceinline__ void mma_tf32(float c[4],
                                         uint32_t a0, uint32_t a1, uint32_t a2, uint32_t a3,
                                         uint32_t b0, uint32_t b1) {
    asm("mma.sync.aligned.m16n8k8.row.col.f32.tf32.tf32.f32 "
        "{%0,%1,%2,%3}, {%4,%5,%6,%7}, {%8,%9}, {%0,%1,%2,%3};"
        : "+f"(c[0]), "+f"(c[1]), "+f"(c[2]), "+f"(c[3])
        : "r"(a0), "r"(a1), "r"(a2), "r"(a3), "r"(b0), "r"(b1));
}

// ---------------- scratch ----------------
__device__ float g_q [4 * 256 * 1024];
__device__ float g_xs[4 * 256 * 1024];
__device__ float g_k [4 * 256 * 1024];
__device__ float g_v [4 * 256 * 1024];
__device__ float g_o [4 * 256 * 1024];
__device__ float g_pos[16 * 1024 * 2];
__device__ uint32_t g_rpeb[8 * 4096];   // per-head padded bf16x2 paired RPE

// ---------------- one-shot RPE repack: g_rpeb[h][x*64+y] = (bf16 T[y][x], bf16 T[y+1][x])
__global__ __launch_bounds__(256)
void rpe_pack(const float* __restrict__ rpe, uint32_t* __restrict__ gR)
{
    const int idx = blockIdx.x * 256 + threadIdx.x;   // 0..32767
    const int h = idx >> 12;
    const int x = (idx >> 6) & 63;
    const int y = idx & 63;
    const float* T = rpe + h * 3969;
    float v0 = (x <= 62 && y <= 62) ? T[y * 63 + x] : 0.f;
    float v1 = (x <= 62 && y <= 61) ? T[(y + 1) * 63 + x] : 0.f;
    uint32_t b0 = (uint32_t)__bfloat16_as_ushort(__float2bfloat16(v0));
    uint32_t b1 = (uint32_t)__bfloat16_as_ushort(__float2bfloat16(v1));
    gR[idx] = b0 | (b1 << 16);
}

// ---------------- tf32 tensor-core SGEMM, double-buffered (R11 config) ------
__device__ __forceinline__ void gemm_tf32_body(const float* __restrict__ Wm,
                                               const float* __restrict__ Xb,
                                               const float* __restrict__ bias,
                                               float* __restrict__ Yb,
                                               int m0, int n0, uint32_t* sm)
{
    uint32_t* As = sm;           // [2][128 m][32 k] stride 36
    uint32_t* Bs = sm + 9216;    // [2][64 n][32 k]  stride 36

    const int tid  = threadIdx.x;
    const int w    = tid >> 5;
    const int lane = tid & 31;
    const int grp  = lane >> 2;
    const int tig  = lane & 3;
    const int mw   = w >> 1;
    const int nw   = w & 1;

    const int a_m = tid >> 5;
    const int a_c = tid & 31;
    const int b_c = tid >> 6;
    const int b_n = tid & 63;

    float acc[2][4][4];
#pragma unroll
    for (int mf = 0; mf < 2; mf++)
#pragma unroll
        for (int nf = 0; nf < 4; nf++)
#pragma unroll
            for (int j = 0; j < 4; j++) acc[mf][nf][j] = 0.f;

    const int rowA0 = (mw * 32 + grp) * 36;
    const int rowB0 = (nw * 32 + grp) * 36;

    float wr[16], xr[8];
#pragma unroll
    for (int t = 0; t < 16; t++)
        wr[t] = Wm[(m0 + t * 8 + a_m) * 256 + a_c];
#pragma unroll
    for (int t = 0; t < 8; t++)
        xr[t] = Xb[(t * 4 + b_c) * 1024 + n0 + b_n];

    for (int kc = 0; kc < 8; kc++) {
        uint32_t* As_b = As + (kc & 1) * 4608;
        uint32_t* Bs_b = Bs + (kc & 1) * 2304;
#pragma unroll
        for (int t = 0; t < 16; t++)
            As_b[(t * 8 + a_m) * 36 + a_c] = cvt_tf32(wr[t]);
#pragma unroll
        for (int t = 0; t < 8; t++)
            Bs_b[b_n * 36 + t * 4 + b_c] = cvt_tf32(xr[t]);
        __syncthreads();

        if (kc < 7) {
            const int k0 = (kc + 1) * 32;
#pragma unroll
            for (int t = 0; t < 16; t++)
                wr[t] = Wm[(m0 + t * 8 + a_m) * 256 + k0 + a_c];
#pragma unroll
            for (int t = 0; t < 8; t++)
                xr[t] = Xb[(k0 + t * 4 + b_c) * 1024 + n0 + b_n];
        }

#pragma unroll
        for (int kk = 0; kk < 4; kk++) {
            const int kb = kk * 8 + tig;
            uint32_t a00 = As_b[rowA0 + kb];
            uint32_t a01 = As_b[rowA0 + 288 + kb];
            uint32_t a02 = As_b[rowA0 + kb + 4];
            uint32_t a03 = As_b[rowA0 + 288 + kb + 4];
            uint32_t a10 = As_b[rowA0 + 576 + kb];
            uint32_t a11 = As_b[rowA0 + 864 + kb];
            uint32_t a12 = As_b[rowA0 + 576 + kb + 4];
            uint32_t a13 = As_b[rowA0 + 864 + kb + 4];
#pragma unroll
            for (int nf = 0; nf < 4; nf++) {
                uint32_t b0 = Bs_b[rowB0 + nf * 288 + kb];
                uint32_t b1 = Bs_b[rowB0 + nf * 288 + kb + 4];
                mma_tf32(acc[0][nf], a00, a01, a02, a03, b0, b1);
                mma_tf32(acc[1][nf], a10, a11, a12, a13, b0, b1);
            }
        }
    }

    const int mr0 = m0 + mw * 32 + grp;
#pragma unroll
    for (int mf = 0; mf < 2; mf++) {
        int r0 = mr0 + mf * 16;
        float b0 = bias[r0], b1 = bias[r0 + 8];
#pragma unroll
        for (int nf = 0; nf < 4; nf++) {
            int col = n0 + nw * 32 + nf * 8 + 2 * tig;
            float2 lo = make_float2(acc[mf][nf][0] + b0, acc[mf][nf][1] + b0);
            float2 hi = make_float2(acc[mf][nf][2] + b1, acc[mf][nf][3] + b1);
            *(float2*)&Yb[r0 * 1024 + col]       = lo;
            *(float2*)&Yb[(r0 + 8) * 1024 + col] = hi;
        }
    }
}

__global__ __launch_bounds__(256, 3)
void gemm_q_tf32(const float* __restrict__ Wm, const float* __restrict__ X,
                 const float* __restrict__ bias, float* __restrict__ Y)
{
    extern __shared__ uint32_t smq[];
    gemm_tf32_body(Wm, X + blockIdx.z * 262144, bias, Y + blockIdx.z * 262144,
                   blockIdx.y * 128, blockIdx.x * 64, smq);
}

__global__ __launch_bounds__(256, 3)
void gemm_kv_tf32(const float* __restrict__ Wk, const float* __restrict__ bk,
                  float* __restrict__ Yk,
                  const float* __restrict__ Wv, const float* __restrict__ bv,
                  float* __restrict__ Yv, const float* __restrict__ X)
{
    extern __shared__ uint32_t smkv[];
    const int my = blockIdx.y;
    const float* Xb = X + blockIdx.z * 262144;
    if (my < 2)
        gemm_tf32_body(Wk, Xb, bk, Yk + blockIdx.z * 262144, my * 128, blockIdx.x * 64, smkv);
    else
        gemm_tf32_body(Wv, Xb, bv, Yv + blockIdx.z * 262144, (my - 2) * 128, blockIdx.x * 64, smkv);
}

// ---------------- offset pipeline: smem-staged conv, activations cached -----
__global__ __launch_bounds__(256)
void offset_kernel(const float* __restrict__ q, const float* __restrict__ w_dw,
                   const float* __restrict__ b_dw, const float* __restrict__ ln_g,
                   const float* __restrict__ ln_b, const float* __restrict__ wpj,
                   float* __restrict__ pos_buf, float* __restrict__ out_pos,
                   float* __restrict__ out_ref)
{
    extern __shared__ float dsm[];
    float* simg = dsm;               // [c][384]
    float* sa   = dsm + 64 * 384;    // [c][256]

    __shared__ float sw[1600];
    __shared__ float sb[64], sg[64], sbt[64], spj0[64], spj1[64];

    const int tid = threadIdx.x;
    for (int t = tid; t < 1600; t += 256) sw[t] = w_dw[t];
    if (tid < 64) {
        sb[tid] = b_dw[tid]; sg[tid] = ln_g[tid]; sbt[tid] = ln_b[tid];
        spj0[tid] = wpj[tid]; spj1[tid] = wpj[64 + tid];
    }

    const int bi = blockIdx.x;
    const int bg = bi >> 2;
    const int i0 = (bi & 3) * 8;
    const float* qb = q + bg * 65536;

    for (int t = tid; t < 24576; t += 256) {
        int c  = t / 384;
        int r2 = t - c * 384;
        int yy = i0 - 2 + (r2 >> 5);
        int col = r2 & 31;
        float vv = 0.f;
        if ((unsigned)yy < 32u) vv = qb[c * 1024 + yy * 32 + col];
        simg[c * 384 + r2] = vv;
    }
    __syncthreads();

    const int li = tid >> 5;
    const int j  = tid & 31;
    const int i  = i0 + li;

    float s1 = 0.f, s2 = 0.f;
    for (int c = 0; c < 64; c++) {
        const float* ic = simg + c * 384 + li * 32;
        const float* wc = sw + c * 25;
        float a = sb[c];
#pragma unroll
        for (int dy = 0; dy < 5; dy++) {
            const float* irow = ic + dy * 32;
#pragma unroll
            for (int dx = 0; dx < 5; dx++) {
                int xx = j + dx - 2;
                float vv = ((unsigned)xx < 32u) ? irow[xx] : 0.f;
                a = fmaf(vv, wc[dy * 5 + dx], a);
            }
        }
        s1 += a;
        s2 = fmaf(a, a, s2);
        sa[c * 256 + tid] = a;
    }
    float mu   = s1 * 0.015625f;
    float var  = s2 * 0.015625f - mu * mu;
    float rstd = rsqrtf(var + 1e-5f);

    float o0 = 0.f, o1 = 0.f;
    for (int c = 0; c < 64; c++) {
        float a  = sa[c * 256 + tid];
        float t2 = fmaf((a - mu) * rstd, sg[c], sbt[c]);
        float gl = 0.5f * t2 * (1.f + erff(t2 * 0.70710678118654752f));
        o0 = fmaf(gl, spj0[c], o0);
        o1 = fmaf(gl, spj1[c], o1);
    }
    float off0 = tanhf(o0) * 0.0625f;
    float off1 = tanhf(o1) * 0.0625f;
    float r0 = (j + 0.5f) * 0.0625f - 1.f;
    float r1 = (i + 0.5f) * 0.0625f - 1.f;
    float P0 = off0 + r0, P1 = off1 + r1;

    const int pix = bi * 256 + tid;
    pos_buf[pix * 2]     = P0;
    pos_buf[pix * 2 + 1] = P1;
    out_pos[pix * 2]     = P0;
    out_pos[pix * 2 + 1] = P1;
    out_ref[pix * 2]     = r0;
    out_ref[pix * 2 + 1] = r1;
}

// ---------------- bilinear sample of x at pos -> xs --------------------------
__global__ __launch_bounds__(256)
void sample_kernel(const float* __restrict__ x, const float* __restrict__ pos_buf,
                   float* __restrict__ xs)
{
    const int w    = threadIdx.x >> 5;
    const int lane = threadIdx.x & 31;
    const int idx  = blockIdx.x * 32 + lane;   // 0..16383
    const float P0 = pos_buf[idx * 2];
    const float P1 = pos_buf[idx * 2 + 1];
    const float gxp = (P1 + 1.f) * 15.5f;
    const float gyp = (P0 + 1.f) * 15.5f;
    float x0f = floorf(gxp), y0f = floorf(gyp);
    float x1f = x0f + 1.f,  y1f = y0f + 1.f;
    float wx1 = gxp - x0f, wx0 = 1.f - wx1;
    float wy1 = gyp - y0f, wy0 = 1.f - wy1;
    bool vx0 = (x0f >= 0.f) && (x0f <= 31.f);
    bool vx1 = (x1f >= 0.f) && (x1f <= 31.f);
    bool vy0 = (y0f >= 0.f) && (y0f <= 31.f);
    bool vy1 = (y1f >= 0.f) && (y1f <= 31.f);
    int X0 = (int)fminf(fmaxf(x0f, 0.f), 31.f);
    int X1 = (int)fminf(fmaxf(x1f, 0.f), 31.f);
    int Y0 = (int)fminf(fmaxf(y0f, 0.f), 31.f);
    int Y1 = (int)fminf(fmaxf(y1f, 0.f), 31.f);
    float w00 = (vy0 && vx0) ? wy0 * wx0 : 0.f;
    float w01 = (vy0 && vx1) ? wy0 * wx1 : 0.f;
    float w10 = (vy1 && vx0) ? wy1 * wx0 : 0.f;
    float w11 = (vy1 && vx1) ? wy1 * wx1 : 0.f;
    int i00 = Y0 * 32 + X0, i01 = Y0 * 32 + X1;
    int i10 = Y1 * 32 + X0, i11 = Y1 * 32 + X1;

    const int bg = idx >> 10, n = idx & 1023;
    const float* xb = x + bg * 65536 + w * 8 * 1024;
    float* xo = xs + bg * 65536 + w * 8 * 1024 + n;
#pragma unroll
    for (int c = 0; c < 8; c++) {
        const float* xc = xb + c * 1024;
        float vout = w00 * xc[i00] + w01 * xc[i01] + w10 * xc[i10] + w11 * xc[i11];
        xo[c * 1024] = vout;
    }
}

// ---------------- RPE bilinear from bf16x2 PAIRED table ----------------------
__device__ __forceinline__ float bias_Pb(const uint32_t* __restrict__ sR,
                                         float gyp, float gxp)
{
    int yi = __float2int_rd(gyp);
    int xi = __float2int_rd(gxp);
    float wy1 = gyp - __int2float_rn(yi);
    float wx1 = gxp - __int2float_rn(xi);
    uint32_t w0 = sR[(xi << 6) + yi];
    uint32_t w1 = sR[(xi << 6) + 64 + yi];
    float p0x = __uint_as_float(w0 << 16);
    float p0y = __uint_as_float(w0 & 0xFFFF0000u);
    float p1x = __uint_as_float(w1 << 16);
    float p1y = __uint_as_float(w1 & 0xFFFF0000u);
    float v0 = fmaf(wy1, p0y - p0x, p0x);
    float v1 = fmaf(wy1, p1y - p1x, p1x);
    return fmaf(wx1, v1 - v0, v0);
}

// ---------------- fused attention (R11 config; RPE table preloaded from gmem)
__global__ __launch_bounds__(256, 3)
void attn_mma(const float* __restrict__ q, const float* __restrict__ k,
              const float* __restrict__ v, const uint32_t* __restrict__ gR,
              const float* __restrict__ pos, float* __restrict__ out)
{
    extern __shared__ float smf[];
    uint32_t* sQ   = (uint32_t*)smf;           // 4608
    uint32_t* sK   = sQ + 4608;                // 2 x 2304
    uint32_t* sV   = sK + 4608;                // 2 x 2304
    float*    sPos = (float*)(sV + 4608);      // 2 x 128
    uint32_t* sRb  = (uint32_t*)(sPos + 256);  // 4096 (bf16x2 pairs)

    const int bh = blockIdx.y;
    const int b  = bh >> 3, h = bh & 7;
    const int gq = h >> 1;
    const int bg = b * 4 + gq;
    const int m0 = blockIdx.x * 128;

    const int tid  = threadIdx.x;
    const int w    = tid >> 5;
    const int lane = tid & 31;
    const int grp  = lane >> 2;
    const int tig  = lane & 3;
    const int pgrp = (grp & 1) ? (grp >> 1) + 4 : (grp >> 1);

    // coalesced preload of the prebuilt paired table
    const uint32_t* gRh = gR + h * 4096;
    for (int t = tid; t < 4096; t += 256) sRb[t] = gRh[t];

    const float* qh = q + (b * 256 + h * 32) * 1024;
    const float* kh = k + (b * 256 + h * 32) * 1024;
    const float* vh = v + (b * 256 + h * 32) * 1024;

    for (int idx = tid; idx < 4096; idx += 256) {
        int c = idx >> 7, mm = idx & 127;
        sQ[mm * 36 + c] = cvt_tf32(qh[c * 1024 + m0 + mm]);
    }

    const int mg0 = m0 + w * 16 + grp;
    const int mg1 = mg0 + 8;
    const float cg00 = fmaf(((mg0 & 31) + 0.5f) * 0.0625f - 1.f, 15.5f, 31.f);
    const float cg01 = fmaf(((mg0 >> 5) + 0.5f) * 0.0625f - 1.f, 15.5f, 31.f);
    const float cg10 = fmaf(((mg1 & 31) + 0.5f) * 0.0625f - 1.f, 15.5f, 31.f);
    const float cg11 = fmaf(((mg1 >> 5) + 0.5f) * 0.0625f - 1.f, 15.5f, 31.f);

    const int rowA0 = (w * 16 + grp) * 36;
    const int rowA1 = rowA0 + 8 * 36;

    float accv[4][4];
#pragma unroll
    for (int vf = 0; vf < 4; vf++)
#pragma unroll
        for (int j = 0; j < 4; j++) accv[vf][j] = 0.f;
    float L0 = 0.f, L1 = 0.f;

    const float scale = 0.17677669529663687f;

    const int st_c = tid >> 6;    // 0..3
    const int st_n = tid & 63;
    float kf[8], vfr[8], posr;
#pragma unroll
    for (int t = 0; t < 8; t++) {
        kf[t]  = kh[(t * 4 + st_c) * 1024 + st_n];
        vfr[t] = vh[(t * 4 + st_c) * 1024 + st_n];
    }
    posr = (tid < 128) ? pos[bg * 2048 + tid] : 0.f;

    for (int nt = 0; nt < 16; nt++) {
        uint32_t* sKb = sK + (nt & 1) * 2304;
        uint32_t* sVb = sV + (nt & 1) * 2304;
        float*    sPb = sPos + (nt & 1) * 128;
#pragma unroll
        for (int t = 0; t < 8; t++) {
            sKb[st_n * 36 + t * 4 + st_c] = cvt_tf32(kf[t]);
            sVb[st_n * 36 + t * 4 + st_c] = cvt_tf32(vfr[t]);
        }
        if (tid < 128) sPb[tid] = posr;
        __syncthreads();

        if (nt < 15) {
            const int n0n = (nt + 1) * 64;
#pragma unroll
            for (int t = 0; t < 8; t++) {
                kf[t]  = kh[(t * 4 + st_c) * 1024 + n0n + st_n];
                vfr[t] = vh[(t * 4 + st_c) * 1024 + n0n + st_n];
            }
            posr = (tid < 128) ? pos[bg * 2048 + n0n * 2 + tid] : 0.f;
        }

        // ---- QK with permuted B rows
        float sc[8][4];
#pragma unroll
        for (int nf = 0; nf < 8; nf++)
#pragma unroll
            for (int j = 0; j < 4; j++) sc[nf][j] = 0.f;

#pragma unroll
        for (int kk = 0; kk < 4; kk++) {
            const int k0 = kk * 8;
            uint32_t a0 = sQ[rowA0 + k0 + tig];
            uint32_t a1 = sQ[rowA1 + k0 + tig];
            uint32_t a2 = sQ[rowA0 + k0 + tig + 4];
            uint32_t a3 = sQ[rowA1 + k0 + tig + 4];
#pragma unroll
            for (int nf = 0; nf < 8; nf++) {
                uint32_t b0 = sKb[(nf * 8 + pgrp) * 36 + k0 + tig];
                uint32_t b1 = sKb[(nf * 8 + pgrp) * 36 + k0 + tig + 4];
                mma_tf32(sc[nf], a0, a1, a2, a3, b0, b1);
            }
        }

        // ---- bias + exp + PV; P stays in registers
#pragma unroll
        for (int nf = 0; nf < 8; nf++) {
            const int kb = nf * 8;
            float2 pA = *(const float2*)&sPb[2 * (kb + tig)];
            float2 pB = *(const float2*)&sPb[2 * (kb + tig + 4)];
            float pb0 = 15.5f * pA.x, pb1 = 15.5f * pA.y;
            float pb2 = 15.5f * pB.x, pb3 = 15.5f * pB.y;
            float e0 = __expf(fmaf(sc[nf][0], scale, bias_Pb(sRb, cg00 - pb0, cg01 - pb1)));
            float e1 = __expf(fmaf(sc[nf][1], scale, bias_Pb(sRb, cg00 - pb2, cg01 - pb3)));
            float e2 = __expf(fmaf(sc[nf][2], scale, bias_Pb(sRb, cg10 - pb0, cg11 - pb1)));
            float e3 = __expf(fmaf(sc[nf][3], scale, bias_Pb(sRb, cg10 - pb2, cg11 - pb3)));
            L0 += e0 + e1;
            L1 += e2 + e3;
            uint32_t a0 = cvt_tf32(e0);
            uint32_t a1 = cvt_tf32(e2);
            uint32_t a2 = cvt_tf32(e1);
            uint32_t a3 = cvt_tf32(e3);
#pragma unroll
            for (int vf = 0; vf < 4; vf++) {
                uint32_t b0 = sVb[(kb + tig) * 36 + vf * 8 + grp];
                uint32_t b1 = sVb[(kb + tig + 4) * 36 + vf * 8 + grp];
                mma_tf32(accv[vf], a0, a1, a2, a3, b0, b1);
            }
        }
    }

    L0 += __shfl_xor_sync(0xffffffffu, L0, 1);
    L0 += __shfl_xor_sync(0xffffffffu, L0, 2);
    L1 += __shfl_xor_sync(0xffffffffu, L1, 1);
    L1 += __shfl_xor_sync(0xffffffffu, L1, 2);
    const float rL0 = 1.f / L0;
    const float rL1 = 1.f / L1;

#pragma unroll
    for (int vf = 0; vf < 4; vf++) {
        int ch = h * 32 + vf * 8 + 2 * tig;
        int base = (b * 256 + ch) * 1024 + mg0;
        out[base]            = accv[vf][0] * rL0;
        out[base + 1024]     = accv[vf][1] * rL0;
        out[base + 8]        = accv[vf][2] * rL1;
        out[base + 1024 + 8] = accv[vf][3] * rL1;
    }
}

// ---------------- launch ----------------
extern "C" void kernel_launch(void* const* d_in, const int* in_sizes, int n_in,
                              void* d_out, int out_size)
{
    const float* x        = (const float*)d_in[0];
    const float* wq       = (const float*)d_in[1];
    const float* bq       = (const float*)d_in[2];
    const float* w_off_dw = (const float*)d_in[3];
    const float* b_off_dw = (const float*)d_in[4];
    const float* ln_g     = (const float*)d_in[5];
    const float* ln_b     = (const float*)d_in[6];
    const float* w_off_pj = (const float*)d_in[7];
    const float* wk       = (const float*)d_in[8];
    const float* bk       = (const float*)d_in[9];
    const float* wv       = (const float*)d_in[10];
    const float* bv       = (const float*)d_in[11];
    const float* wo       = (const float*)d_in[12];
    const float* bo       = (const float*)d_in[13];
    const float* rpe      = (const float*)d_in[14];
    float* out = (float*)d_out;

    float *qb, *xsb, *kb, *vb, *ob, *posb;
    uint32_t* rpebb;
    cudaGetSymbolAddress((void**)&qb,    g_q);
    cudaGetSymbolAddress((void**)&xsb,   g_xs);
    cudaGetSymbolAddress((void**)&kb,    g_k);
    cudaGetSymbolAddress((void**)&vb,    g_v);
    cudaGetSymbolAddress((void**)&ob,    g_o);
    cudaGetSymbolAddress((void**)&posb,  g_pos);
    cudaGetSymbolAddress((void**)&rpebb, g_rpeb);

    const int attn_smem = 72704;
    cudaFuncSetAttribute(attn_mma, cudaFuncAttributeMaxDynamicSharedMemorySize, attn_smem);
    const int gem_smem = 55296;
    cudaFuncSetAttribute(gemm_q_tf32, cudaFuncAttributeMaxDynamicSharedMemorySize, gem_smem);
    cudaFuncSetAttribute(gemm_kv_tf32, cudaFuncAttributeMaxDynamicSharedMemorySize, gem_smem);
    const int off_smem = 163840;
    cudaFuncSetAttribute(offset_kernel, cudaFuncAttributeMaxDynamicSharedMemorySize, off_smem);

    rpe_pack<<<128, 256>>>(rpe, rpebb);
    gemm_q_tf32<<<dim3(16, 2, 4), 256, gem_smem>>>(wq, x, bq, qb);
    offset_kernel<<<64, 256, off_smem>>>(qb, w_off_dw, b_off_dw, ln_g, ln_b, w_off_pj,
                                         posb, out + 1048576, out + 1048576 + 32768);
    sample_kernel<<<512, 256>>>(x, posb, xsb);
    gemm_kv_tf32<<<dim3(16, 4, 4), 256, gem_smem>>>(wk, bk, kb, wv, bv, vb, xsb);
    attn_mma<<<dim3(8, 32), 256, attn_smem>>>(qb, kb, vb, rpebb, posb, ob);
    gemm_q_tf32<<<dim3(16, 2, 4), 256, gem_smem>>>(wo, ob, bo, out);
}

// round 16
// speedup vs baseline: 1.0825x; 1.0040x over previous
#include <cuda_runtime.h>
#include <cuda_bf16.h>
#include <math.h>
#include <stdint.h>

// B=4, C=256, H=W=32, NH=8, HC=32, G=4, GC=64, ns=1024, KK=5, ORF=2
typedef unsigned long long u64;

__device__ __forceinline__ uint32_t cvt_tf32(float x) {
    uint32_t r;
    asm("cvt.rna.tf32.f32 %0, %1;" : "=r"(r) : "f"(x));
    return r;
}
__device__ __forceinline__ void mma_tf32(float c[4],
                                         uint32_t a0, uint32_t a1, uint32_t a2, uint32_t a3,
                                         uint32_t b0, uint32_t b1) {
    asm("mma.sync.aligned.m16n8k8.row.col.f32.tf32.tf32.f32 "
        "{%0,%1,%2,%3}, {%4,%5,%6,%7}, {%8,%9}, {%0,%1,%2,%3};"
        : "+f"(c[0]), "+f"(c[1]), "+f"(c[2]), "+f"(c[3])
        : "r"(a0), "r"(a1), "r"(a2), "r"(a3), "r"(b0), "r"(b1));
}

// ---------------- scratch ----------------
__device__ float g_q [4 * 256 * 1024];
__device__ float g_xs[4 * 256 * 1024];
__device__ float g_k [4 * 256 * 1024];
__device__ float g_v [4 * 256 * 1024];
__device__ float g_o [4 * 256 * 1024];
__device__ float g_pos[16 * 1024 * 2];
__device__ uint32_t g_rpeb[8 * 4096];   // per-head padded bf16x2 paired RPE

// ---------------- one-shot RPE repack ----------------------------------------
__global__ __launch_bounds__(256)
void rpe_pack(const float* __restrict__ rpe, uint32_t* __restrict__ gR)
{
    const int idx = blockIdx.x * 256 + threadIdx.x;   // 0..32767
    const int h = idx >> 12;
    const int x = (idx >> 6) & 63;
    const int y = idx & 63;
    const float* T = rpe + h * 3969;
    float v0 = (x <= 62 && y <= 62) ? T[y * 63 + x] : 0.f;
    float v1 = (x <= 62 && y <= 61) ? T[(y + 1) * 63 + x] : 0.f;
    uint32_t b0 = (uint32_t)__bfloat16_as_ushort(__float2bfloat16(v0));
    uint32_t b1 = (uint32_t)__bfloat16_as_ushort(__float2bfloat16(v1));
    gR[idx] = b0 | (b1 << 16);
}

// ---------------- tf32 tensor-core SGEMM, double-buffered (R11 config) ------
__device__ __forceinline__ void gemm_tf32_body(const float* __restrict__ Wm,
                                               const float* __restrict__ Xb,
                                               const float* __restrict__ bias,
                                               float* __restrict__ Yb,
                                               int m0, int n0, uint32_t* sm)
{
    uint32_t* As = sm;           // [2][128 m][32 k] stride 36
    uint32_t* Bs = sm + 9216;    // [2][64 n][32 k]  stride 36

    const int tid  = threadIdx.x;
    const int w    = tid >> 5;
    const int lane = tid & 31;
    const int grp  = lane >> 2;
    const int tig  = lane & 3;
    const int mw   = w >> 1;
    const int nw   = w & 1;

    const int a_m = tid >> 5;
    const int a_c = tid & 31;
    const int b_c = tid >> 6;
    const int b_n = tid & 63;

    float acc[2][4][4];
#pragma unroll
    for (int mf = 0; mf < 2; mf++)
#pragma unroll
        for (int nf = 0; nf < 4; nf++)
#pragma unroll
            for (int j = 0; j < 4; j++) acc[mf][nf][j] = 0.f;

    const int rowA0 = (mw * 32 + grp) * 36;
    const int rowB0 = (nw * 32 + grp) * 36;

    float wr[16], xr[8];
#pragma unroll
    for (int t = 0; t < 16; t++)
        wr[t] = Wm[(m0 + t * 8 + a_m) * 256 + a_c];
#pragma unroll
    for (int t = 0; t < 8; t++)
        xr[t] = Xb[(t * 4 + b_c) * 1024 + n0 + b_n];

    for (int kc = 0; kc < 8; kc++) {
        uint32_t* As_b = As + (kc & 1) * 4608;
        uint32_t* Bs_b = Bs + (kc & 1) * 2304;
#pragma unroll
        for (int t = 0; t < 16; t++)
            As_b[(t * 8 + a_m) * 36 + a_c] = cvt_tf32(wr[t]);
#pragma unroll
        for (int t = 0; t < 8; t++)
            Bs_b[b_n * 36 + t * 4 + b_c] = cvt_tf32(xr[t]);
        __syncthreads();

        if (kc < 7) {
            const int k0 = (kc + 1) * 32;
#pragma unroll
            for (int t = 0; t < 16; t++)
                wr[t] = Wm[(m0 + t * 8 + a_m) * 256 + k0 + a_c];
#pragma unroll
            for (int t = 0; t < 8; t++)
                xr[t] = Xb[(k0 + t * 4 + b_c) * 1024 + n0 + b_n];
        }

#pragma unroll
        for (int kk = 0; kk < 4; kk++) {
            const int kb = kk * 8 + tig;
            uint32_t a00 = As_b[rowA0 + kb];
            uint32_t a01 = As_b[rowA0 + 288 + kb];
            uint32_t a02 = As_b[rowA0 + kb + 4];
            uint32_t a03 = As_b[rowA0 + 288 + kb + 4];
            uint32_t a10 = As_b[rowA0 + 576 + kb];
            uint32_t a11 = As_b[rowA0 + 864 + kb];
            uint32_t a12 = As_b[rowA0 + 576 + kb + 4];
            uint32_t a13 = As_b[rowA0 + 864 + kb + 4];
#pragma unroll
            for (int nf = 0; nf < 4; nf++) {
                uint32_t b0 = Bs_b[rowB0 + nf * 288 + kb];
                uint32_t b1 = Bs_b[rowB0 + nf * 288 + kb + 4];
                mma_tf32(acc[0][nf], a00, a01, a02, a03, b0, b1);
                mma_tf32(acc[1][nf], a10, a11, a12, a13, b0, b1);
            }
        }
    }

    const int mr0 = m0 + mw * 32 + grp;
#pragma unroll
    for (int mf = 0; mf < 2; mf++) {
        int r0 = mr0 + mf * 16;
        float b0 = bias[r0], b1 = bias[r0 + 8];
#pragma unroll
        for (int nf = 0; nf < 4; nf++) {
            int col = n0 + nw * 32 + nf * 8 + 2 * tig;
            float2 lo = make_float2(acc[mf][nf][0] + b0, acc[mf][nf][1] + b0);
            float2 hi = make_float2(acc[mf][nf][2] + b1, acc[mf][nf][3] + b1);
            *(float2*)&Yb[r0 * 1024 + col]       = lo;
            *(float2*)&Yb[(r0 + 8) * 1024 + col] = hi;
        }
    }
}

__global__ __launch_bounds__(256, 3)
void gemm_q_tf32(const float* __restrict__ Wm, const float* __restrict__ X,
                 const float* __restrict__ bias, float* __restrict__ Y)
{
    extern __shared__ uint32_t smq[];
    gemm_tf32_body(Wm, X + blockIdx.z * 262144, bias, Y + blockIdx.z * 262144,
                   blockIdx.y * 128, blockIdx.x * 64, smq);
}

__global__ __launch_bounds__(256, 3)
void gemm_kv_tf32(const float* __restrict__ Wk, const float* __restrict__ bk,
                  float* __restrict__ Yk,
                  const float* __restrict__ Wv, const float* __restrict__ bv,
                  float* __restrict__ Yv, const float* __restrict__ X)
{
    extern __shared__ uint32_t smkv[];
    const int my = blockIdx.y;
    const float* Xb = X + blockIdx.z * 262144;
    if (my < 2)
        gemm_tf32_body(Wk, Xb, bk, Yk + blockIdx.z * 262144, my * 128, blockIdx.x * 64, smkv);
    else
        gemm_tf32_body(Wv, Xb, bv, Yv + blockIdx.z * 262144, (my - 2) * 128, blockIdx.x * 64, smkv);
}

// ---------------- offset pipeline: smem-staged conv, activations cached -----
__global__ __launch_bounds__(256)
void offset_kernel(const float* __restrict__ q, const float* __restrict__ w_dw,
                   const float* __restrict__ b_dw, const float* __restrict__ ln_g,
                   const float* __restrict__ ln_b, const float* __restrict__ wpj,
                   float* __restrict__ pos_buf, float* __restrict__ out_pos,
                   float* __restrict__ out_ref)
{
    extern __shared__ float dsm[];
    float* simg = dsm;               // [c][384]
    float* sa   = dsm + 64 * 384;    // [c][256]

    __shared__ float sw[1600];
    __shared__ float sb[64], sg[64], sbt[64], spj0[64], spj1[64];

    const int tid = threadIdx.x;
    for (int t = tid; t < 1600; t += 256) sw[t] = w_dw[t];
    if (tid < 64) {
        sb[tid] = b_dw[tid]; sg[tid] = ln_g[tid]; sbt[tid] = ln_b[tid];
        spj0[tid] = wpj[tid]; spj1[tid] = wpj[64 + tid];
    }

    const int bi = blockIdx.x;
    const int bg = bi >> 2;
    const int i0 = (bi & 3) * 8;
    const float* qb = q + bg * 65536;

    for (int t = tid; t < 24576; t += 256) {
        int c  = t / 384;
        int r2 = t - c * 384;
        int yy = i0 - 2 + (r2 >> 5);
        int col = r2 & 31;
        float vv = 0.f;
        if ((unsigned)yy < 32u) vv = qb[c * 1024 + yy * 32 + col];
        simg[c * 384 + r2] = vv;
    }
    __syncthreads();

    const int li = tid >> 5;
    const int j  = tid & 31;
    const int i  = i0 + li;

    float s1 = 0.f, s2 = 0.f;
    for (int c = 0; c < 64; c++) {
        const float* ic = simg + c * 384 + li * 32;
        const float* wc = sw + c * 25;
        float a = sb[c];
#pragma unroll
        for (int dy = 0; dy < 5; dy++) {
            const float* irow = ic + dy * 32;
#pragma unroll
            for (int dx = 0; dx < 5; dx++) {
                int xx = j + dx - 2;
                float vv = ((unsigned)xx < 32u) ? irow[xx] : 0.f;
                a = fmaf(vv, wc[dy * 5 + dx], a);
            }
        }
        s1 += a;
        s2 = fmaf(a, a, s2);
        sa[c * 256 + tid] = a;
    }
    float mu   = s1 * 0.015625f;
    float var  = s2 * 0.015625f - mu * mu;
    float rstd = rsqrtf(var + 1e-5f);

    float o0 = 0.f, o1 = 0.f;
    for (int c = 0; c < 64; c++) {
        float a  = sa[c * 256 + tid];
        float t2 = fmaf((a - mu) * rstd, sg[c], sbt[c]);
        float gl = 0.5f * t2 * (1.f + erff(t2 * 0.70710678118654752f));
        o0 = fmaf(gl, spj0[c], o0);
        o1 = fmaf(gl, spj1[c], o1);
    }
    float off0 = tanhf(o0) * 0.0625f;
    float off1 = tanhf(o1) * 0.0625f;
    float r0 = (j + 0.5f) * 0.0625f - 1.f;
    float r1 = (i + 0.5f) * 0.0625f - 1.f;
    float P0 = off0 + r0, P1 = off1 + r1;

    const int pix = bi * 256 + tid;
    pos_buf[pix * 2]     = P0;
    pos_buf[pix * 2 + 1] = P1;
    out_pos[pix * 2]     = P0;
    out_pos[pix * 2 + 1] = P1;
    out_ref[pix * 2]     = r0;
    out_ref[pix * 2 + 1] = r1;
}

// ---------------- bilinear sample, smem-staged image -------------------------
// grid (16 bg, 8 chgroup), 256 threads. Block stages its 8-channel slice of
// x[bg] (32 KB) into smem; each thread samples 4 points x 8 channels via LDS.
__global__ __launch_bounds__(256)
void sample_kernel(const float* __restrict__ x, const float* __restrict__ pos_buf,
                   float* __restrict__ xs)
{
    __shared__ float sx[8 * 1024];
    const int tid = threadIdx.x;
    const int bg  = blockIdx.x;
    const int cg0 = blockIdx.y * 8;
    const float* xb = x + bg * 65536 + cg0 * 1024;

    // stage 8 channels coalesced (float4)
    for (int t = tid; t < 2048; t += 256)
        *(float4*)&sx[t * 4] = *(const float4*)&xb[t * 4];
    __syncthreads();

    float* xo = xs + bg * 65536 + cg0 * 1024;

#pragma unroll
    for (int p = 0; p < 4; p++) {
        const int n = p * 256 + tid;          // point index within bg
        const float2 P = *(const float2*)&pos_buf[(bg * 1024 + n) * 2];
        const float gxp = (P.y + 1.f) * 15.5f;
        const float gyp = (P.x + 1.f) * 15.5f;
        float x0f = floorf(gxp), y0f = floorf(gyp);
        float x1f = x0f + 1.f,  y1f = y0f + 1.f;
        float wx1 = gxp - x0f, wx0 = 1.f - wx1;
        float wy1 = gyp - y0f, wy0 = 1.f - wy1;
        bool vx0 = (x0f >= 0.f) && (x0f <= 31.f);
        bool vx1 = (x1f >= 0.f) && (x1f <= 31.f);
        bool vy0 = (y0f >= 0.f) && (y0f <= 31.f);
        bool vy1 = (y1f >= 0.f) && (y1f <= 31.f);
        int X0 = (int)fminf(fmaxf(x0f, 0.f), 31.f);
        int X1 = (int)fminf(fmaxf(x1f, 0.f), 31.f);
        int Y0 = (int)fminf(fmaxf(y0f, 0.f), 31.f);
        int Y1 = (int)fminf(fmaxf(y1f, 0.f), 31.f);
        float w00 = (vy0 && vx0) ? wy0 * wx0 : 0.f;
        float w01 = (vy0 && vx1) ? wy0 * wx1 : 0.f;
        float w10 = (vy1 && vx0) ? wy1 * wx0 : 0.f;
        float w11 = (vy1 && vx1) ? wy1 * wx1 : 0.f;
        int i00 = Y0 * 32 + X0, i01 = Y0 * 32 + X1;
        int i10 = Y1 * 32 + X0, i11 = Y1 * 32 + X1;

#pragma unroll
        for (int c = 0; c < 8; c++) {
            const float* sc_ = sx + c * 1024;
            float vout = w00 * sc_[i00] + w01 * sc_[i01]
                       + w10 * sc_[i10] + w11 * sc_[i11];
            xo[c * 1024 + n] = vout;
        }
    }
}

// ---------------- RPE bilinear from bf16x2 PAIRED table ----------------------
__device__ __forceinline__ float bias_Pb(const uint32_t* __restrict__ sR,
                                         float gyp, float gxp)
{
    int yi = __float2int_rd(gyp);
    int xi = __float2int_rd(gxp);
    float wy1 = gyp - __int2float_rn(yi);
    float wx1 = gxp - __int2float_rn(xi);
    uint32_t w0 = sR[(xi << 6) + yi];
    uint32_t w1 = sR[(xi << 6) + 64 + yi];
    float p0x = __uint_as_float(w0 << 16);
    float p0y = __uint_as_float(w0 & 0xFFFF0000u);
    float p1x = __uint_as_float(w1 << 16);
    float p1y = __uint_as_float(w1 & 0xFFFF0000u);
    float v0 = fmaf(wy1, p0y - p0x, p0x);
    float v1 = fmaf(wy1, p1y - p1x, p1x);
    return fmaf(wx1, v1 - v0, v0);
}

// ---------------- fused attention (R11 config; RPE table preloaded from gmem)
__global__ __launch_bounds__(256, 3)
void attn_mma(const float* __restrict__ q, const float* __restrict__ k,
              const float* __restrict__ v, const uint32_t* __restrict__ gR,
              const float* __restrict__ pos, float* __restrict__ out)
{
    extern __shared__ float smf[];
    uint32_t* sQ   = (uint32_t*)smf;           // 4608
    uint32_t* sK   = sQ + 4608;                // 2 x 2304
    uint32_t* sV   = sK + 4608;                // 2 x 2304
    float*    sPos = (float*)(sV + 4608);      // 2 x 128
    uint32_t* sRb  = (uint32_t*)(sPos + 256);  // 4096 (bf16x2 pairs)

    const int bh = blockIdx.y;
    const int b  = bh >> 3, h = bh & 7;
    const int gq = h >> 1;
    const int bg = b * 4 + gq;
    const int m0 = blockIdx.x * 128;

    const int tid  = threadIdx.x;
    const int w    = tid >> 5;
    const int lane = tid & 31;
    const int grp  = lane >> 2;
    const int tig  = lane & 3;
    const int pgrp = (grp & 1) ? (grp >> 1) + 4 : (grp >> 1);

    const uint32_t* gRh = gR + h * 4096;
    for (int t = tid; t < 4096; t += 256) sRb[t] = gRh[t];

    const float* qh = q + (b * 256 + h * 32) * 1024;
    const float* kh = k + (b * 256 + h * 32) * 1024;
    const float* vh = v + (b * 256 + h * 32) * 1024;

    for (int idx = tid; idx < 4096; idx += 256) {
        int c = idx >> 7, mm = idx & 127;
        sQ[mm * 36 + c] = cvt_tf32(qh[c * 1024 + m0 + mm]);
    }

    const int mg0 = m0 + w * 16 + grp;
    const int mg1 = mg0 + 8;
    const float cg00 = fmaf(((mg0 & 31) + 0.5f) * 0.0625f - 1.f, 15.5f, 31.f);
    const float cg01 = fmaf(((mg0 >> 5) + 0.5f) * 0.0625f - 1.f, 15.5f, 31.f);
    const float cg10 = fmaf(((mg1 & 31) + 0.5f) * 0.0625f - 1.f, 15.5f, 31.f);
    const float cg11 = fmaf(((mg1 >> 5) + 0.5f) * 0.0625f - 1.f, 15.5f, 31.f);

    const int rowA0 = (w * 16 + grp) * 36;
    const int rowA1 = rowA0 + 8 * 36;

    float accv[4][4];
#pragma unroll
    for (int vf = 0; vf < 4; vf++)
#pragma unroll
        for (int j = 0; j < 4; j++) accv[vf][j] = 0.f;
    float L0 = 0.f, L1 = 0.f;

    const float scale = 0.17677669529663687f;

    const int st_c = tid >> 6;    // 0..3
    const int st_n = tid & 63;
    float kf[8], vfr[8], posr;
#pragma unroll
    for (int t = 0; t < 8; t++) {
        kf[t]  = kh[(t * 4 + st_c) * 1024 + st_n];
        vfr[t] = vh[(t * 4 + st_c) * 1024 + st_n];
    }
    posr = (tid < 128) ? pos[bg * 2048 + tid] : 0.f;

    for (int nt = 0; nt < 16; nt++) {
        uint32_t* sKb = sK + (nt & 1) * 2304;
        uint32_t* sVb = sV + (nt & 1) * 2304;
        float*    sPb = sPos + (nt & 1) * 128;
#pragma unroll
        for (int t = 0; t < 8; t++) {
            sKb[st_n * 36 + t * 4 + st_c] = cvt_tf32(kf[t]);
            sVb[st_n * 36 + t * 4 + st_c] = cvt_tf32(vfr[t]);
        }
        if (tid < 128) sPb[tid] = posr;
        __syncthreads();

        if (nt < 15) {
            const int n0n = (nt + 1) * 64;
#pragma unroll
            for (int t = 0; t < 8; t++) {
                kf[t]  = kh[(t * 4 + st_c) * 1024 + n0n + st_n];
                vfr[t] = vh[(t * 4 + st_c) * 1024 + n0n + st_n];
            }
            posr = (tid < 128) ? pos[bg * 2048 + n0n * 2 + tid] : 0.f;
        }

        // ---- QK with permuted B rows
        float sc[8][4];
#pragma unroll
        for (int nf = 0; nf < 8; nf++)
#pragma unroll
            for (int j = 0; j < 4; j++) sc[nf][j] = 0.f;

#pragma unroll
        for (int kk = 0; kk < 4; kk++) {
            const int k0 = kk * 8;
            uint32_t a0 = sQ[rowA0 + k0 + tig];
            uint32_t a1 = sQ[rowA1 + k0 + tig];
            uint32_t a2 = sQ[rowA0 + k0 + tig + 4];
            uint32_t a3 = sQ[rowA1 + k0 + tig + 4];
#pragma unroll
            for (int nf = 0; nf < 8; nf++) {
                uint32_t b0 = sKb[(nf * 8 + pgrp) * 36 + k0 + tig];
                uint32_t b1 = sKb[(nf * 8 + pgrp) * 36 + k0 + tig + 4];
                mma_tf32(sc[nf], a0, a1, a2, a3, b0, b1);
            }
        }

        // ---- bias + exp + PV; P stays in registers
#pragma unroll
        for (int nf = 0; nf < 8; nf++) {
            const int kb = nf * 8;
            float2 pA = *(const float2*)&sPb[2 * (kb + tig)];
            float2 pB = *(const float2*)&sPb[2 * (kb + tig + 4)];
            float pb0 = 15.5f * pA.x, pb1 = 15.5f * pA.y;
            float pb2 = 15.5f * pB.x, pb3 = 15.5f * pB.y;
            float e0 = __expf(fmaf(sc[nf][0], scale, bias_Pb(sRb, cg00 - pb0, cg01 - pb1)));
            float e1 = __expf(fmaf(sc[nf][1], scale, bias_Pb(sRb, cg00 - pb2, cg01 - pb3)));
            float e2 = __expf(fmaf(sc[nf][2], scale, bias_Pb(sRb, cg10 - pb0, cg11 - pb1)));
            float e3 = __expf(fmaf(sc[nf][3], scale, bias_Pb(sRb, cg10 - pb2, cg11 - pb3)));
            L0 += e0 + e1;
            L1 += e2 + e3;
            uint32_t a0 = cvt_tf32(e0);
            uint32_t a1 = cvt_tf32(e2);
            uint32_t a2 = cvt_tf32(e1);
            uint32_t a3 = cvt_tf32(e3);
#pragma unroll
            for (int vf = 0; vf < 4; vf++) {
                uint32_t b0 = sVb[(kb + tig) * 36 + vf * 8 + grp];
                uint32_t b1 = sVb[(kb + tig + 4) * 36 + vf * 8 + grp];
                mma_tf32(accv[vf], a0, a1, a2, a3, b0, b1);
            }
        }
    }

    L0 += __shfl_xor_sync(0xffffffffu, L0, 1);
    L0 += __shfl_xor_sync(0xffffffffu, L0, 2);
    L1 += __shfl_xor_sync(0xffffffffu, L1, 1);
    L1 += __shfl_xor_sync(0xffffffffu, L1, 2);
    const float rL0 = 1.f / L0;
    const float rL1 = 1.f / L1;

#pragma unroll
    for (int vf = 0; vf < 4; vf++) {
        int ch = h * 32 + vf * 8 + 2 * tig;
        int base = (b * 256 + ch) * 1024 + mg0;
        out[base]            = accv[vf][0] * rL0;
        out[base + 1024]     = accv[vf][1] * rL0;
        out[base + 8]        = accv[vf][2] * rL1;
        out[base + 1024 + 8] = accv[vf][3] * rL1;
    }
}

// ---------------- launch ----------------
extern "C" void kernel_launch(void* const* d_in, const int* in_sizes, int n_in,
                              void* d_out, int out_size)
{
    const float* x        = (const float*)d_in[0];
    const float* wq       = (const float*)d_in[1];
    const float* bq       = (const float*)d_in[2];
    const float* w_off_dw = (const float*)d_in[3];
    const float* b_off_dw = (const float*)d_in[4];
    const float* ln_g     = (const float*)d_in[5];
    const float* ln_b     = (const float*)d_in[6];
    const float* w_off_pj = (const float*)d_in[7];
    const float* wk       = (const float*)d_in[8];
    const float* bk       = (const float*)d_in[9];
    const float* wv       = (const float*)d_in[10];
    const float* bv       = (const float*)d_in[11];
    const float* wo       = (const float*)d_in[12];
    const float* bo       = (const float*)d_in[13];
    const float* rpe      = (const float*)d_in[14];
    float* out = (float*)d_out;

    float *qb, *xsb, *kb, *vb, *ob, *posb;
    uint32_t* rpebb;
    cudaGetSymbolAddress((void**)&qb,    g_q);
    cudaGetSymbolAddress((void**)&xsb,   g_xs);
    cudaGetSymbolAddress((void**)&kb,    g_k);
    cudaGetSymbolAddress((void**)&vb,    g_v);
    cudaGetSymbolAddress((void**)&ob,    g_o);
    cudaGetSymbolAddress((void**)&posb,  g_pos);
    cudaGetSymbolAddress((void**)&rpebb, g_rpeb);

    const int attn_smem = 72704;
    cudaFuncSetAttribute(attn_mma, cudaFuncAttributeMaxDynamicSharedMemorySize, attn_smem);
    const int gem_smem = 55296;
    cudaFuncSetAttribute(gemm_q_tf32, cudaFuncAttributeMaxDynamicSharedMemorySize, gem_smem);
    cudaFuncSetAttribute(gemm_kv_tf32, cudaFuncAttributeMaxDynamicSharedMemorySize, gem_smem);
    const int off_smem = 163840;
    cudaFuncSetAttribute(offset_kernel, cudaFuncAttributeMaxDynamicSharedMemorySize, off_smem);

    rpe_pack<<<128, 256>>>(rpe, rpebb);
    gemm_q_tf32<<<dim3(16, 2, 4), 256, gem_smem>>>(wq, x, bq, qb);
    offset_kernel<<<64, 256, off_smem>>>(qb, w_off_dw, b_off_dw, ln_g, ln_b, w_off_pj,
                                         posb, out + 1048576, out + 1048576 + 32768);
    sample_kernel<<<dim3(16, 8), 256>>>(x, posb, xsb);
    gemm_kv_tf32<<<dim3(16, 4, 4), 256, gem_smem>>>(wk, bk, kb, wv, bv, vb, xsb);
    attn_mma<<<dim3(8, 32), 256, attn_smem>>>(qb, kb, vb, rpebb, posb, ob);
    gemm_q_tf32<<<dim3(16, 2, 4), 256, gem_smem>>>(wo, ob, bo, out);
}

// round 17
// speedup vs baseline: 1.0846x; 1.0019x over previous
#include <cuda_runtime.h>
#include <cuda_bf16.h>
#include <math.h>
#include <stdint.h>

// B=4, C=256, H=W=32, NH=8, HC=32, G=4, GC=64, ns=1024, KK=5, ORF=2
typedef unsigned long long u64;

__device__ __forceinline__ uint32_t cvt_tf32(float x) {
    uint32_t r;
    asm("cvt.rna.tf32.f32 %0, %1;" : "=r"(r) : "f"(x));
    return r;
}
__device__ __forceinline__ void mma_tf32(float c[4],
                                         uint32_t a0, uint32_t a1, uint32_t a2, uint32_t a3,
                                         uint32_t b0, uint32_t b1) {
    asm("mma.sync.aligned.m16n8k8.row.col.f32.tf32.tf32.f32 "
        "{%0,%1,%2,%3}, {%4,%5,%6,%7}, {%8,%9}, {%0,%1,%2,%3};"
        : "+f"(c[0]), "+f"(c[1]), "+f"(c[2]), "+f"(c[3])
        : "r"(a0), "r"(a1), "r"(a2), "r"(a3), "r"(b0), "r"(b1));
}

// ---------------- scratch ----------------
__device__ float g_q [4 * 256 * 1024];
__device__ float g_xs[4 * 256 * 1024];
__device__ float g_k [4 * 256 * 1024];
__device__ float g_v [4 * 256 * 1024];
__device__ float g_o [4 * 256 * 1024];
__device__ float g_pos[16 * 1024 * 2];
__device__ uint32_t g_rpeb[8 * 4096];   // per-head padded bf16x2 paired RPE

// ---------------- one-shot RPE repack ----------------------------------------
__global__ __launch_bounds__(256)
void rpe_pack(const float* __restrict__ rpe, uint32_t* __restrict__ gR)
{
    const int idx = blockIdx.x * 256 + threadIdx.x;   // 0..32767
    const int h = idx >> 12;
    const int x = (idx >> 6) & 63;
    const int y = idx & 63;
    const float* T = rpe + h * 3969;
    float v0 = (x <= 62 && y <= 62) ? T[y * 63 + x] : 0.f;
    float v1 = (x <= 62 && y <= 61) ? T[(y + 1) * 63 + x] : 0.f;
    uint32_t b0 = (uint32_t)__bfloat16_as_ushort(__float2bfloat16(v0));
    uint32_t b1 = (uint32_t)__bfloat16_as_ushort(__float2bfloat16(v1));
    gR[idx] = b0 | (b1 << 16);
}

// ---------------- tf32 tensor-core SGEMM, double-buffered (R11 config) ------
__device__ __forceinline__ void gemm_tf32_body(const float* __restrict__ Wm,
                                               const float* __restrict__ Xb,
                                               const float* __restrict__ bias,
                                               float* __restrict__ Yb,
                                               int m0, int n0, uint32_t* sm)
{
    uint32_t* As = sm;           // [2][128 m][32 k] stride 36
    uint32_t* Bs = sm + 9216;    // [2][64 n][32 k]  stride 36

    const int tid  = threadIdx.x;
    const int w    = tid >> 5;
    const int lane = tid & 31;
    const int grp  = lane >> 2;
    const int tig  = lane & 3;
    const int mw   = w >> 1;
    const int nw   = w & 1;

    const int a_m = tid >> 5;
    const int a_c = tid & 31;
    const int b_c = tid >> 6;
    const int b_n = tid & 63;

    float acc[2][4][4];
#pragma unroll
    for (int mf = 0; mf < 2; mf++)
#pragma unroll
        for (int nf = 0; nf < 4; nf++)
#pragma unroll
            for (int j = 0; j < 4; j++) acc[mf][nf][j] = 0.f;

    const int rowA0 = (mw * 32 + grp) * 36;
    const int rowB0 = (nw * 32 + grp) * 36;

    float wr[16], xr[8];
#pragma unroll
    for (int t = 0; t < 16; t++)
        wr[t] = Wm[(m0 + t * 8 + a_m) * 256 + a_c];
#pragma unroll
    for (int t = 0; t < 8; t++)
        xr[t] = Xb[(t * 4 + b_c) * 1024 + n0 + b_n];

    for (int kc = 0; kc < 8; kc++) {
        uint32_t* As_b = As + (kc & 1) * 4608;
        uint32_t* Bs_b = Bs + (kc & 1) * 2304;
#pragma unroll
        for (int t = 0; t < 16; t++)
            As_b[(t * 8 + a_m) * 36 + a_c] = cvt_tf32(wr[t]);
#pragma unroll
        for (int t = 0; t < 8; t++)
            Bs_b[b_n * 36 + t * 4 + b_c] = cvt_tf32(xr[t]);
        __syncthreads();

        if (kc < 7) {
            const int k0 = (kc + 1) * 32;
#pragma unroll
            for (int t = 0; t < 16; t++)
                wr[t] = Wm[(m0 + t * 8 + a_m) * 256 + k0 + a_c];
#pragma unroll
            for (int t = 0; t < 8; t++)
                xr[t] = Xb[(k0 + t * 4 + b_c) * 1024 + n0 + b_n];
        }

#pragma unroll
        for (int kk = 0; kk < 4; kk++) {
            const int kb = kk * 8 + tig;
            uint32_t a00 = As_b[rowA0 + kb];
            uint32_t a01 = As_b[rowA0 + 288 + kb];
            uint32_t a02 = As_b[rowA0 + kb + 4];
            uint32_t a03 = As_b[rowA0 + 288 + kb + 4];
            uint32_t a10 = As_b[rowA0 + 576 + kb];
            uint32_t a11 = As_b[rowA0 + 864 + kb];
            uint32_t a12 = As_b[rowA0 + 576 + kb + 4];
            uint32_t a13 = As_b[rowA0 + 864 + kb + 4];
#pragma unroll
            for (int nf = 0; nf < 4; nf++) {
                uint32_t b0 = Bs_b[rowB0 + nf * 288 + kb];
                uint32_t b1 = Bs_b[rowB0 + nf * 288 + kb + 4];
                mma_tf32(acc[0][nf], a00, a01, a02, a03, b0, b1);
                mma_tf32(acc[1][nf], a10, a11, a12, a13, b0, b1);
            }
        }
    }

    const int mr0 = m0 + mw * 32 + grp;
#pragma unroll
    for (int mf = 0; mf < 2; mf++) {
        int r0 = mr0 + mf * 16;
        float b0 = bias[r0], b1 = bias[r0 + 8];
#pragma unroll
        for (int nf = 0; nf < 4; nf++) {
            int col = n0 + nw * 32 + nf * 8 + 2 * tig;
            float2 lo = make_float2(acc[mf][nf][0] + b0, acc[mf][nf][1] + b0);
            float2 hi = make_float2(acc[mf][nf][2] + b1, acc[mf][nf][3] + b1);
            *(float2*)&Yb[r0 * 1024 + col]       = lo;
            *(float2*)&Yb[(r0 + 8) * 1024 + col] = hi;
        }
    }
}

__global__ __launch_bounds__(256, 3)
void gemm_q_tf32(const float* __restrict__ Wm, const float* __restrict__ X,
                 const float* __restrict__ bias, float* __restrict__ Y)
{
    extern __shared__ uint32_t smq[];
    gemm_tf32_body(Wm, X + blockIdx.z * 262144, bias, Y + blockIdx.z * 262144,
                   blockIdx.y * 128, blockIdx.x * 64, smq);
}

__global__ __launch_bounds__(256, 3)
void gemm_kv_tf32(const float* __restrict__ Wk, const float* __restrict__ bk,
                  float* __restrict__ Yk,
                  const float* __restrict__ Wv, const float* __restrict__ bv,
                  float* __restrict__ Yv, const float* __restrict__ X)
{
    extern __shared__ uint32_t smkv[];
    const int my = blockIdx.y;
    const float* Xb = X + blockIdx.z * 262144;
    if (my < 2)
        gemm_tf32_body(Wk, Xb, bk, Yk + blockIdx.z * 262144, my * 128, blockIdx.x * 64, smkv);
    else
        gemm_tf32_body(Wv, Xb, bv, Yv + blockIdx.z * 262144, (my - 2) * 128, blockIdx.x * 64, smkv);
}

// ---------------- offset pipeline: smem-staged conv, activations cached -----
__global__ __launch_bounds__(256)
void offset_kernel(const float* __restrict__ q, const float* __restrict__ w_dw,
                   const float* __restrict__ b_dw, const float* __restrict__ ln_g,
                   const float* __restrict__ ln_b, const float* __restrict__ wpj,
                   float* __restrict__ pos_buf, float* __restrict__ out_pos,
                   float* __restrict__ out_ref)
{
    extern __shared__ float dsm[];
    float* simg = dsm;               // [c][384]
    float* sa   = dsm + 64 * 384;    // [c][256]

    __shared__ float sw[1600];
    __shared__ float sb[64], sg[64], sbt[64], spj0[64], spj1[64];

    const int tid = threadIdx.x;
    for (int t = tid; t < 1600; t += 256) sw[t] = w_dw[t];
    if (tid < 64) {
        sb[tid] = b_dw[tid]; sg[tid] = ln_g[tid]; sbt[tid] = ln_b[tid];
        spj0[tid] = wpj[tid]; spj1[tid] = wpj[64 + tid];
    }

    const int bi = blockIdx.x;
    const int bg = bi >> 2;
    const int i0 = (bi & 3) * 8;
    const float* qb = q + bg * 65536;

    for (int t = tid; t < 24576; t += 256) {
        int c  = t / 384;
        int r2 = t - c * 384;
        int yy = i0 - 2 + (r2 >> 5);
        int col = r2 & 31;
        float vv = 0.f;
        if ((unsigned)yy < 32u) vv = qb[c * 1024 + yy * 32 + col];
        simg[c * 384 + r2] = vv;
    }
    __syncthreads();

    const int li = tid >> 5;
    const int j  = tid & 31;
    const int i  = i0 + li;

    float s1 = 0.f, s2 = 0.f;
    for (int c = 0; c < 64; c++) {
        const float* ic = simg + c * 384 + li * 32;
        const float* wc = sw + c * 25;
        float a = sb[c];
#pragma unroll
        for (int dy = 0; dy < 5; dy++) {
            const float* irow = ic + dy * 32;
#pragma unroll
            for (int dx = 0; dx < 5; dx++) {
                int xx = j + dx - 2;
                float vv = ((unsigned)xx < 32u) ? irow[xx] : 0.f;
                a = fmaf(vv, wc[dy * 5 + dx], a);
            }
        }
        s1 += a;
        s2 = fmaf(a, a, s2);
        sa[c * 256 + tid] = a;
    }
    float mu   = s1 * 0.015625f;
    float var  = s2 * 0.015625f - mu * mu;
    float rstd = rsqrtf(var + 1e-5f);

    float o0 = 0.f, o1 = 0.f;
    for (int c = 0; c < 64; c++) {
        float a  = sa[c * 256 + tid];
        float t2 = fmaf((a - mu) * rstd, sg[c], sbt[c]);
        float gl = 0.5f * t2 * (1.f + erff(t2 * 0.70710678118654752f));
        o0 = fmaf(gl, spj0[c], o0);
        o1 = fmaf(gl, spj1[c], o1);
    }
    float off0 = tanhf(o0) * 0.0625f;
    float off1 = tanhf(o1) * 0.0625f;
    float r0 = (j + 0.5f) * 0.0625f - 1.f;
    float r1 = (i + 0.5f) * 0.0625f - 1.f;
    float P0 = off0 + r0, P1 = off1 + r1;

    const int pix = bi * 256 + tid;
    pos_buf[pix * 2]     = P0;
    pos_buf[pix * 2 + 1] = P1;
    out_pos[pix * 2]     = P0;
    out_pos[pix * 2 + 1] = P1;
    out_ref[pix * 2]     = r0;
    out_ref[pix * 2 + 1] = r1;
}

// ---------------- bilinear sample, smem-staged image, 1024-thread blocks -----
// grid (16 bg, 8 chgroup) x 1024 threads. Block stages its 8-channel slice of
// x[bg] (32 KB); thread = one point, 8 channels. 32 warps/SM for latency hiding.
__global__ __launch_bounds__(1024)
void sample_kernel(const float* __restrict__ x, const float* __restrict__ pos_buf,
                   float* __restrict__ xs)
{
    __shared__ float sx[8 * 1024];
    const int tid = threadIdx.x;
    const int bg  = blockIdx.x;
    const int cg0 = blockIdx.y * 8;
    const float* xb = x + bg * 65536 + cg0 * 1024;

    // stage 8 channels coalesced (float4): 2 per thread
    *(float4*)&sx[tid * 4]        = *(const float4*)&xb[tid * 4];
    *(float4*)&sx[(tid + 1024) * 4] = *(const float4*)&xb[(tid + 1024) * 4];
    __syncthreads();

    const int n = tid;
    const float2 P = *(const float2*)&pos_buf[(bg * 1024 + n) * 2];
    const float gxp = (P.y + 1.f) * 15.5f;
    const float gyp = (P.x + 1.f) * 15.5f;
    float x0f = floorf(gxp), y0f = floorf(gyp);
    float x1f = x0f + 1.f,  y1f = y0f + 1.f;
    float wx1 = gxp - x0f, wx0 = 1.f - wx1;
    float wy1 = gyp - y0f, wy0 = 1.f - wy1;
    bool vx0 = (x0f >= 0.f) && (x0f <= 31.f);
    bool vx1 = (x1f >= 0.f) && (x1f <= 31.f);
    bool vy0 = (y0f >= 0.f) && (y0f <= 31.f);
    bool vy1 = (y1f >= 0.f) && (y1f <= 31.f);
    int X0 = (int)fminf(fmaxf(x0f, 0.f), 31.f);
    int X1 = (int)fminf(fmaxf(x1f, 0.f), 31.f);
    int Y0 = (int)fminf(fmaxf(y0f, 0.f), 31.f);
    int Y1 = (int)fminf(fmaxf(y1f, 0.f), 31.f);
    float w00 = (vy0 && vx0) ? wy0 * wx0 : 0.f;
    float w01 = (vy0 && vx1) ? wy0 * wx1 : 0.f;
    float w10 = (vy1 && vx0) ? wy1 * wx0 : 0.f;
    float w11 = (vy1 && vx1) ? wy1 * wx1 : 0.f;
    int i00 = Y0 * 32 + X0, i01 = Y0 * 32 + X1;
    int i10 = Y1 * 32 + X0, i11 = Y1 * 32 + X1;

    float* xo = xs + bg * 65536 + cg0 * 1024 + n;
#pragma unroll
    for (int c = 0; c < 8; c++) {
        const float* sc_ = sx + c * 1024;
        float vout = w00 * sc_[i00] + w01 * sc_[i01]
                   + w10 * sc_[i10] + w11 * sc_[i11];
        xo[c * 1024] = vout;
    }
}

// ---------------- RPE bilinear from bf16x2 PAIRED table ----------------------
__device__ __forceinline__ float bias_Pb(const uint32_t* __restrict__ sR,
                                         float gyp, float gxp)
{
    int yi = __float2int_rd(gyp);
    int xi = __float2int_rd(gxp);
    float wy1 = gyp - __int2float_rn(yi);
    float wx1 = gxp - __int2float_rn(xi);
    uint32_t w0 = sR[(xi << 6) + yi];
    uint32_t w1 = sR[(xi << 6) + 64 + yi];
    float p0x = __uint_as_float(w0 << 16);
    float p0y = __uint_as_float(w0 & 0xFFFF0000u);
    float p1x = __uint_as_float(w1 << 16);
    float p1y = __uint_as_float(w1 & 0xFFFF0000u);
    float v0 = fmaf(wy1, p0y - p0x, p0x);
    float v1 = fmaf(wy1, p1y - p1x, p1x);
    return fmaf(wx1, v1 - v0, v0);
}

// ---------------- fused attention (R11 config; RPE table preloaded from gmem)
__global__ __launch_bounds__(256, 3)
void attn_mma(const float* __restrict__ q, const float* __restrict__ k,
              const float* __restrict__ v, const uint32_t* __restrict__ gR,
              const float* __restrict__ pos, float* __restrict__ out)
{
    extern __shared__ float smf[];
    uint32_t* sQ   = (uint32_t*)smf;           // 4608
    uint32_t* sK   = sQ + 4608;                // 2 x 2304
    uint32_t* sV   = sK + 4608;                // 2 x 2304
    float*    sPos = (float*)(sV + 4608);      // 2 x 128
    uint32_t* sRb  = (uint32_t*)(sPos + 256);  // 4096 (bf16x2 pairs)

    const int bh = blockIdx.y;
    const int b  = bh >> 3, h = bh & 7;
    const int gq = h >> 1;
    const int bg = b * 4 + gq;
    const int m0 = blockIdx.x * 128;

    const int tid  = threadIdx.x;
    const int w    = tid >> 5;
    const int lane = tid & 31;
    const int grp  = lane >> 2;
    const int tig  = lane & 3;
    const int pgrp = (grp & 1) ? (grp >> 1) + 4 : (grp >> 1);

    const uint32_t* gRh = gR + h * 4096;
    for (int t = tid; t < 4096; t += 256) sRb[t] = gRh[t];

    const float* qh = q + (b * 256 + h * 32) * 1024;
    const float* kh = k + (b * 256 + h * 32) * 1024;
    const float* vh = v + (b * 256 + h * 32) * 1024;

    for (int idx = tid; idx < 4096; idx += 256) {
        int c = idx >> 7, mm = idx & 127;
        sQ[mm * 36 + c] = cvt_tf32(qh[c * 1024 + m0 + mm]);
    }

    const int mg0 = m0 + w * 16 + grp;
    const int mg1 = mg0 + 8;
    const float cg00 = fmaf(((mg0 & 31) + 0.5f) * 0.0625f - 1.f, 15.5f, 31.f);
    const float cg01 = fmaf(((mg0 >> 5) + 0.5f) * 0.0625f - 1.f, 15.5f, 31.f);
    const float cg10 = fmaf(((mg1 & 31) + 0.5f) * 0.0625f - 1.f, 15.5f, 31.f);
    const float cg11 = fmaf(((mg1 >> 5) + 0.5f) * 0.0625f - 1.f, 15.5f, 31.f);

    const int rowA0 = (w * 16 + grp) * 36;
    const int rowA1 = rowA0 + 8 * 36;

    float accv[4][4];
#pragma unroll
    for (int vf = 0; vf < 4; vf++)
#pragma unroll
        for (int j = 0; j < 4; j++) accv[vf][j] = 0.f;
    float L0 = 0.f, L1 = 0.f;

    const float scale = 0.17677669529663687f;

    const int st_c = tid >> 6;    // 0..3
    const int st_n = tid & 63;
    float kf[8], vfr[8], posr;
#pragma unroll
    for (int t = 0; t < 8; t++) {
        kf[t]  = kh[(t * 4 + st_c) * 1024 + st_n];
        vfr[t] = vh[(t * 4 + st_c) * 1024 + st_n];
    }
    posr = (tid < 128) ? pos[bg * 2048 + tid] : 0.f;

    for (int nt = 0; nt < 16; nt++) {
        uint32_t* sKb = sK + (nt & 1) * 2304;
        uint32_t* sVb = sV + (nt & 1) * 2304;
        float*    sPb = sPos + (nt & 1) * 128;
#pragma unroll
        for (int t = 0; t < 8; t++) {
            sKb[st_n * 36 + t * 4 + st_c] = cvt_tf32(kf[t]);
            sVb[st_n * 36 + t * 4 + st_c] = cvt_tf32(vfr[t]);
        }
        if (tid < 128) sPb[tid] = posr;
        __syncthreads();

        if (nt < 15) {
            const int n0n = (nt + 1) * 64;
#pragma unroll
            for (int t = 0; t < 8; t++) {
                kf[t]  = kh[(t * 4 + st_c) * 1024 + n0n + st_n];
                vfr[t] = vh[(t * 4 + st_c) * 1024 + n0n + st_n];
            }
            posr = (tid < 128) ? pos[bg * 2048 + n0n * 2 + tid] : 0.f;
        }

        // ---- QK with permuted B rows
        float sc[8][4];
#pragma unroll
        for (int nf = 0; nf < 8; nf++)
#pragma unroll
            for (int j = 0; j < 4; j++) sc[nf][j] = 0.f;

#pragma unroll
        for (int kk = 0; kk < 4; kk++) {
            const int k0 = kk * 8;
            uint32_t a0 = sQ[rowA0 + k0 + tig];
            uint32_t a1 = sQ[rowA1 + k0 + tig];
            uint32_t a2 = sQ[rowA0 + k0 + tig + 4];
            uint32_t a3 = sQ[rowA1 + k0 + tig + 4];
#pragma unroll
            for (int nf = 0; nf < 8; nf++) {
                uint32_t b0 = sKb[(nf * 8 + pgrp) * 36 + k0 + tig];
                uint32_t b1 = sKb[(nf * 8 + pgrp) * 36 + k0 + tig + 4];
                mma_tf32(sc[nf], a0, a1, a2, a3, b0, b1);
            }
        }

        // ---- bias + exp + PV; P stays in registers
#pragma unroll
        for (int nf = 0; nf < 8; nf++) {
            const int kb = nf * 8;
            float2 pA = *(const float2*)&sPb[2 * (kb + tig)];
            float2 pB = *(const float2*)&sPb[2 * (kb + tig + 4)];
            float pb0 = 15.5f * pA.x, pb1 = 15.5f * pA.y;
            float pb2 = 15.5f * pB.x, pb3 = 15.5f * pB.y;
            float e0 = __expf(fmaf(sc[nf][0], scale, bias_Pb(sRb, cg00 - pb0, cg01 - pb1)));
            float e1 = __expf(fmaf(sc[nf][1], scale, bias_Pb(sRb, cg00 - pb2, cg01 - pb3)));
            float e2 = __expf(fmaf(sc[nf][2], scale, bias_Pb(sRb, cg10 - pb0, cg11 - pb1)));
            float e3 = __expf(fmaf(sc[nf][3], scale, bias_Pb(sRb, cg10 - pb2, cg11 - pb3)));
            L0 += e0 + e1;
            L1 += e2 + e3;
            uint32_t a0 = cvt_tf32(e0);
            uint32_t a1 = cvt_tf32(e2);
            uint32_t a2 = cvt_tf32(e1);
            uint32_t a3 = cvt_tf32(e3);
#pragma unroll
            for (int vf = 0; vf < 4; vf++) {
                uint32_t b0 = sVb[(kb + tig) * 36 + vf * 8 + grp];
                uint32_t b1 = sVb[(kb + tig + 4) * 36 + vf * 8 + grp];
                mma_tf32(accv[vf], a0, a1, a2, a3, b0, b1);
            }
        }
    }

    L0 += __shfl_xor_sync(0xffffffffu, L0, 1);
    L0 += __shfl_xor_sync(0xffffffffu, L0, 2);
    L1 += __shfl_xor_sync(0xffffffffu, L1, 1);
    L1 += __shfl_xor_sync(0xffffffffu, L1, 2);
    const float rL0 = 1.f / L0;
    const float rL1 = 1.f / L1;

#pragma unroll
    for (int vf = 0; vf < 4; vf++) {
        int ch = h * 32 + vf * 8 + 2 * tig;
        int base = (b * 256 + ch) * 1024 + mg0;
        out[base]            = accv[vf][0] * rL0;
        out[base + 1024]     = accv[vf][1] * rL0;
        out[base + 8]        = accv[vf][2] * rL1;
        out[base + 1024 + 8] = accv[vf][3] * rL1;
    }
}

// ---------------- launch ----------------
extern "C" void kernel_launch(void* const* d_in, const int* in_sizes, int n_in,
                              void* d_out, int out_size)
{
    const float* x        = (const float*)d_in[0];
    const float* wq       = (const float*)d_in[1];
    const float* bq       = (const float*)d_in[2];
    const float* w_off_dw = (const float*)d_in[3];
    const float* b_off_dw = (const float*)d_in[4];
    const float* ln_g     = (const float*)d_in[5];
    const float* ln_b     = (const float*)d_in[6];
    const float* w_off_pj = (const float*)d_in[7];
    const float* wk       = (const float*)d_in[8];
    const float* bk       = (const float*)d_in[9];
    const float* wv       = (const float*)d_in[10];
    const float* bv       = (const float*)d_in[11];
    const float* wo       = (const float*)d_in[12];
    const float* bo       = (const float*)d_in[13];
    const float* rpe      = (const float*)d_in[14];
    float* out = (float*)d_out;

    float *qb, *xsb, *kb, *vb, *ob, *posb;
    uint32_t* rpebb;
    cudaGetSymbolAddress((void**)&qb,    g_q);
    cudaGetSymbolAddress((void**)&xsb,   g_xs);
    cudaGetSymbolAddress((void**)&kb,    g_k);
    cudaGetSymbolAddress((void**)&vb,    g_v);
    cudaGetSymbolAddress((void**)&ob,    g_o);
    cudaGetSymbolAddress((void**)&posb,  g_pos);
    cudaGetSymbolAddress((void**)&rpebb, g_rpeb);

    const int attn_smem = 72704;
    cudaFuncSetAttribute(attn_mma, cudaFuncAttributeMaxDynamicSharedMemorySize, attn_smem);
    const int gem_smem = 55296;
    cudaFuncSetAttribute(gemm_q_tf32, cudaFuncAttributeMaxDynamicSharedMemorySize, gem_smem);
    cudaFuncSetAttribute(gemm_kv_tf32, cudaFuncAttributeMaxDynamicSharedMemorySize, gem_smem);
    const int off_smem = 163840;
    cudaFuncSetAttribute(offset_kernel, cudaFuncAttributeMaxDynamicSharedMemorySize, off_smem);

    rpe_pack<<<128, 256>>>(rpe, rpebb);
    gemm_q_tf32<<<dim3(16, 2, 4), 256, gem_smem>>>(wq, x, bq, qb);
    offset_kernel<<<64, 256, off_smem>>>(qb, w_off_dw, b_off_dw, ln_g, ln_b, w_off_pj,
                                         posb, out + 1048576, out + 1048576 + 32768);
    sample_kernel<<<dim3(16, 8), 1024>>>(x, posb, xsb);
    gemm_kv_tf32<<<dim3(16, 4, 4), 256, gem_smem>>>(wk, bk, kb, wv, bv, vb, xsb);
    attn_mma<<<dim3(8, 32), 256, attn_smem>>>(qb, kb, vb, rpebb, posb, ob);
    gemm_q_tf32<<<dim3(16, 2, 4), 256, gem_smem>>>(wo, ob, bo, out);
}